// round 13
// baseline (speedup 1.0000x reference)
#include <cuda_runtime.h>
#include <cuda_bf16.h>

#define E_TOT   100000
#define NN      50000
#define POOL_BLKS 296
#define ROWS_PER_BLK 169
#define TILE_E  64
#define GRID_MAIN ((E_TOT + TILE_E - 1) / TILE_E)
#define EA_U    68      /* sEAhi/sEAlo row stride in uints (64 data + 4 pad) */
#define QK_S    260     /* sQK row stride (floats) */
#define SCALE   0.08838834764831845f   /* 1/sqrt(128) */

// ---------------- device scratch ----------------
__device__ float g_partial[POOL_BLKS * 512];
__device__ float g_pooled[512];
__device__ float g_kg[512];
__device__ float g_vg[512];
__device__ float g_M[512];          // [4][128] = v_g @ wo_g^T
__device__ float g_kqg[512];        // [128][4]
__device__ float g_cgs[4];
__device__ float g_c0[256];         // bq_l @ wk_l
__device__ float g_bias2[128];      // bv_l @ wo_l^T + bo_l
// B matrices pre-split to bf16 hi/lo in m16n8k16 fragment order:
__device__ uint4 g_Cb4[256 * 8 * 4];    // C:  n=256, k=128 (kg 0..7)
__device__ uint4 g_W2b4[128 * 16 * 4];  // W2: n=128, k=256 (kg 0..15)

__device__ __forceinline__ float dot4(float4 a, float4 b) {
    return a.x * b.x + a.y * b.y + a.z * b.z + a.w * b.w;
}

__device__ __forceinline__ void mma16(float* d, const unsigned* a, unsigned b0, unsigned b1) {
    asm volatile(
        "mma.sync.aligned.m16n8k16.row.col.f32.bf16.bf16.f32 "
        "{%0,%1,%2,%3}, {%4,%5,%6,%7}, {%8,%9}, {%0,%1,%2,%3};"
        : "+f"(d[0]), "+f"(d[1]), "+f"(d[2]), "+f"(d[3])
        : "r"(a[0]), "r"(a[1]), "r"(a[2]), "r"(a[3]), "r"(b0), "r"(b1));
}

__device__ __forceinline__ unsigned bf2_as_u(__nv_bfloat162 h) {
    return *(unsigned*)&h;
}
__device__ __forceinline__ __nv_bfloat162 u_as_bf2(unsigned u) {
    return *(__nv_bfloat162*)&u;
}

// split float pair -> hi bf16x2, lo bf16x2
__device__ __forceinline__ void split_bf2(float x, float y, unsigned& hi, unsigned& lo) {
    __nv_bfloat162 h = __float22bfloat162_rn(make_float2(x, y));
    float2 hf = __bfloat1622float2(h);
    __nv_bfloat162 l = __float22bfloat162_rn(make_float2(x - hf.x, y - hf.y));
    hi = bf2_as_u(h);
    lo = bf2_as_u(l);
}

// write one fp32 value as pre-split bf16 hi/lo into fragment-ordered array.
__device__ __forceinline__ void write_b_split(__nv_bfloat16* base, int n, int k,
                                              int kgs, float v) {
    int kg = k >> 4, r = k & 15;
    int word, t4;
    if (r < 8) { t4 = r >> 1; word = 0; }
    else       { t4 = (r - 8) >> 1; word = 1; }
    int half = r & 1;
    size_t bidx = ((((size_t)(n * kgs + kg) * 4 + t4) * 4 + word) * 2 + half);
    __nv_bfloat16 hi = __float2bfloat16(v);
    __nv_bfloat16 lo = __float2bfloat16(v - __bfloat162float(hi));
    base[bidx] = hi;
    base[bidx + 4] = lo;
}

// ---------------- kernel 1: pool partials + C + W2 + c0 + bias2 ----------
// blocks 0..295: pool partial (float4, 4 rows in flight);
// 296..423: C k-rows; 424..679: W2 k-cols; 680: c0; 681: bias2.
__global__ void k1_precompute(const float* __restrict__ gf,
                              const float* __restrict__ wq_l,
                              const float* __restrict__ wk_l,
                              const float* __restrict__ wv_l,
                              const float* __restrict__ wo_l,
                              const float* __restrict__ bq_l,
                              const float* __restrict__ bv_l,
                              const float* __restrict__ bo_l) {
    extern __shared__ float st[];
    int b = blockIdx.x, t = threadIdx.x;
    if (b < POOL_BLKS) {
        int r0 = b * ROWS_PER_BLK;
        int nrows = NN - r0;
        if (nrows > ROWS_PER_BLK) nrows = ROWS_PER_BLK;
        int tq = t & 127;          // float4 column group
        int tr = t >> 7;           // row offset 0..3
        const float4* p4 = (const float4*)gf;
        float4 a0 = make_float4(0.f, 0.f, 0.f, 0.f);
        float4 a1 = a0, a2 = a0, a3 = a0;
        for (int r = 0; r < nrows; r += 16) {
            int rr0 = r + tr;
            int rr1 = r + 4 + tr;
            int rr2 = r + 8 + tr;
            int rr3 = r + 12 + tr;
            if (rr0 < nrows) {
                float4 v = p4[(size_t)(r0 + rr0) * 128 + tq];
                a0.x += v.x; a0.y += v.y; a0.z += v.z; a0.w += v.w;
            }
            if (rr1 < nrows) {
                float4 v = p4[(size_t)(r0 + rr1) * 128 + tq];
                a1.x += v.x; a1.y += v.y; a1.z += v.z; a1.w += v.w;
            }
            if (rr2 < nrows) {
                float4 v = p4[(size_t)(r0 + rr2) * 128 + tq];
                a2.x += v.x; a2.y += v.y; a2.z += v.z; a2.w += v.w;
            }
            if (rr3 < nrows) {
                float4 v = p4[(size_t)(r0 + rr3) * 128 + tq];
                a3.x += v.x; a3.y += v.y; a3.z += v.z; a3.w += v.w;
            }
        }
        float4 acc = make_float4((a0.x + a1.x) + (a2.x + a3.x),
                                 (a0.y + a1.y) + (a2.y + a3.y),
                                 (a0.z + a1.z) + (a2.z + a3.z),
                                 (a0.w + a1.w) + (a2.w + a3.w));
        float4* st4 = (float4*)st;
        st4[tr * 128 + tq] = acc;
        __syncthreads();
        if (t < 128) {
            float4 s0 = st4[t], s1 = st4[128 + t], s2 = st4[256 + t], s3 = st4[384 + t];
            float4 s = make_float4((s0.x + s1.x) + (s2.x + s3.x),
                                   (s0.y + s1.y) + (s2.y + s3.y),
                                   (s0.z + s1.z) + (s2.z + s3.z),
                                   (s0.w + s1.w) + (s2.w + s3.w));
            ((float4*)g_partial)[b * 128 + t] = s;
        }
    } else if (b < POOL_BLKS + 128) {
        int i = b - POOL_BLKS;      // C k-row 0..127
        if (t < 256) {
            float a = 0.f;
            for (int h = 0; h < 128; ++h)
                a += __ldg(&wq_l[h * 128 + i]) * wk_l[h * 256 + t];
            write_b_split((__nv_bfloat16*)g_Cb4, t, i, 8, a);
        }
    } else if (b < POOL_BLKS + 384) {
        int j = b - (POOL_BLKS + 128);   // W2 k-index 0..255
        for (int idx = t; idx < 16384; idx += 512) {
            int h = idx >> 7, m = idx & 127;
            st[m * 132 + h] = wo_l[idx];
        }
        __syncthreads();
        if (t < 128) {
            float a = 0.f;
            for (int m = 0; m < 128; ++m)
                a += __ldg(&wv_l[m * 256 + j]) * st[m * 132 + t];
            write_b_split((__nv_bfloat16*)g_W2b4, t, j, 16, a);
        }
    } else if (b == POOL_BLKS + 384) {
        if (t < 256) {
            float a = 0.f;
            for (int h = 0; h < 128; ++h) a += bq_l[h] * wk_l[h * 256 + t];
            g_c0[t] = a;
        }
    } else {
        for (int idx = t; idx < 16384; idx += 512) {
            int h = idx >> 7, m = idx & 127;
            st[m * 132 + h] = wo_l[idx];
        }
        __syncthreads();
        if (t < 128) {
            float a = 0.f;
            for (int m = 0; m < 128; ++m) a += bv_l[m] * st[m * 132 + t];
            g_bias2[t] = a + bo_l[t];
        }
    }
}

// ---------------- kernel 2: pooled + global-path small matrices ----------
// Fused staging: {wk_g, wv_g} -> {k_g, v_g}; then {wo_g, wq_g} -> {M, kqg, cgs}.
__global__ void k2_small(const float* __restrict__ wk_g,
                         const float* __restrict__ wv_g,
                         const float* __restrict__ wo_g,
                         const float* __restrict__ wq_g,
                         const float* __restrict__ bk_g,
                         const float* __restrict__ bv_g,
                         const float* __restrict__ bq_g,
                         float* __restrict__ out_pooled) {
    extern __shared__ float st[];       // 2 x 16896 floats
    float* st2 = st + 16896;
    int t = threadIdx.x;

    float s = 0.f;
    #pragma unroll 4
    for (int b = 0; b < POOL_BLKS; ++b) s += g_partial[b * 512 + t];
    s *= (1.0f / NN);
    g_pooled[t] = s;
    out_pooled[t] = s;

    // stage wk_g and wv_g together (transposed)
    for (int idx = t; idx < 16384; idx += 512) {
        int h = idx >> 7, j = idx & 127;
        st[j * 132 + h]  = wk_g[idx];
        st2[j * 132 + h] = wv_g[idx];
    }
    __syncthreads();
    {
        int si = t >> 7, h = t & 127;
        float a = 0.f, a2 = 0.f;
        for (int j = 0; j < 128; ++j) {
            float p = g_pooled[si * 128 + j];
            a  += p * st[j * 132 + h];
            a2 += p * st2[j * 132 + h];
        }
        g_kg[t] = a + bk_g[h];
        g_vg[t] = a2 + bv_g[h];
    }
    __syncthreads();

    // stage wo_g and wq_g together (transposed)
    for (int idx = t; idx < 16384; idx += 512) {
        int h = idx >> 7, m = idx & 127;
        st[m * 132 + h]  = wo_g[idx];
        st2[m * 132 + h] = wq_g[idx];
    }
    __syncthreads();
    {
        int si = t >> 7, h = t & 127;
        float a = 0.f;
        for (int m = 0; m < 128; ++m) a += g_vg[si * 128 + m] * st[m * 132 + h];
        g_M[t] = a;
    }
    {
        int i = t >> 2, si = t & 3;
        float a = 0.f;
        for (int h = 0; h < 128; ++h) a += st2[i * 132 + h] * g_kg[si * 128 + h];
        g_kqg[i * 4 + si] = a;
    }
    if (t < 4) {
        float a = 0.f;
        for (int h = 0; h < 128; ++h) a += bq_g[h] * g_kg[t * 128 + h];
        g_cgs[t] = a;
    }
}

// ---------------- kernel 3: fused per-edge kernel (256 thr, 2 CTA/SM) ----
// (R9 main kernel verbatim — measured 239.1 us)
__global__ void __launch_bounds__(256, 2)
main_edge_kernel(const float* __restrict__ ea_g,
                 const float* __restrict__ gf,
                 const int* __restrict__ ei,
                 const float* __restrict__ bo_g,
                 float* __restrict__ out,
                 float* __restrict__ attn_out) {
    extern __shared__ float smem[];
    unsigned* sEAhi = (unsigned*)smem;            // 64*68 uints
    unsigned* sEAlo = sEAhi + 64 * EA_U;          // 64*68 uints
    float*    sQK   = smem + 2 * 64 * EA_U;       // 64*260 floats
    const int tid  = threadIdx.x;
    const int wid  = tid >> 5;    // 0..7
    const int lane = tid & 31;
    const int g    = lane >> 2;   // 0..7
    const int t4   = lane & 3;    // 0..3
    const int e0   = blockIdx.x * TILE_E;

    // stage edge_attr tile pre-split to bf16 hi/lo (zero-fill OOB rows)
    for (int idx = tid; idx < 2048; idx += 256) {
        int r = idx >> 5, c = idx & 31;          // c: float4 col (k = 4c)
        float4 v = make_float4(0.f, 0.f, 0.f, 0.f);
        if (e0 + r < E_TOT) v = ((const float4*)ea_g)[(size_t)(e0 + r) * 32 + c];
        unsigned h0, l0, h1, l1;
        split_bf2(v.x, v.y, h0, l0);
        split_bf2(v.z, v.w, h1, l1);
        sEAhi[r * EA_U + 2 * c]     = h0;
        sEAhi[r * EA_U + 2 * c + 1] = h1;
        sEAlo[r * EA_U + 2 * c]     = l0;
        sEAlo[r * EA_U + 2 * c + 1] = l1;
    }
    __syncthreads();

    // ---- Phase A: qk[64][256] = ea @ C + c0 (bf16 m16n8k16, 3-term) ----
    {
        const int wm = wid >> 2;          // 0..1
        const int wn = wid & 3;           // 0..3
        const int m0 = wm * 32;
        const int n0 = wn * 64;
        float acc[2][8][4];
        #pragma unroll
        for (int am = 0; am < 2; ++am)
            #pragma unroll
            for (int bn = 0; bn < 8; ++bn)
                #pragma unroll
                for (int q = 0; q < 4; ++q) acc[am][bn][q] = 0.f;

        uint4 bpc[4], bpn[4];
        #pragma unroll
        for (int b2 = 0; b2 < 4; ++b2)
            bpc[b2] = __ldg(&g_Cb4[((n0 + 8 * b2 + g) * 8 + 0) * 4 + t4]);

        #pragma unroll 1
        for (int kg = 0; kg < 8; ++kg) {
            unsigned Ah[2][4], Al[2][4];
            #pragma unroll
            for (int am = 0; am < 2; ++am) {
                int R = m0 + 16 * am;
                Ah[am][0] = sEAhi[(R + g)     * EA_U + kg * 8 + t4];
                Ah[am][1] = sEAhi[(R + g + 8) * EA_U + kg * 8 + t4];
                Ah[am][2] = sEAhi[(R + g)     * EA_U + kg * 8 + 4 + t4];
                Ah[am][3] = sEAhi[(R + g + 8) * EA_U + kg * 8 + 4 + t4];
                Al[am][0] = sEAlo[(R + g)     * EA_U + kg * 8 + t4];
                Al[am][1] = sEAlo[(R + g + 8) * EA_U + kg * 8 + t4];
                Al[am][2] = sEAlo[(R + g)     * EA_U + kg * 8 + 4 + t4];
                Al[am][3] = sEAlo[(R + g + 8) * EA_U + kg * 8 + 4 + t4];
            }
            #pragma unroll
            for (int b2 = 0; b2 < 4; ++b2)
                bpn[b2] = __ldg(&g_Cb4[((n0 + 32 + 8 * b2 + g) * 8 + kg) * 4 + t4]);
            #pragma unroll
            for (int b2 = 0; b2 < 4; ++b2) {
                #pragma unroll
                for (int am = 0; am < 2; ++am) {
                    mma16(acc[am][b2], Ah[am], bpc[b2].x, bpc[b2].y);
                    mma16(acc[am][b2], Ah[am], bpc[b2].z, bpc[b2].w);
                    mma16(acc[am][b2], Al[am], bpc[b2].x, bpc[b2].y);
                }
            }
            if (kg < 7) {
                #pragma unroll
                for (int b2 = 0; b2 < 4; ++b2)
                    bpc[b2] = __ldg(&g_Cb4[((n0 + 8 * b2 + g) * 8 + kg + 1) * 4 + t4]);
            }
            #pragma unroll
            for (int b2 = 0; b2 < 4; ++b2) {
                #pragma unroll
                for (int am = 0; am < 2; ++am) {
                    mma16(acc[am][4 + b2], Ah[am], bpn[b2].x, bpn[b2].y);
                    mma16(acc[am][4 + b2], Ah[am], bpn[b2].z, bpn[b2].w);
                    mma16(acc[am][4 + b2], Al[am], bpn[b2].x, bpn[b2].y);
                }
            }
        }

        // epilogue: qk + c0 -> sQK
        #pragma unroll
        for (int am = 0; am < 2; ++am) {
            #pragma unroll
            for (int bn = 0; bn < 8; ++bn) {
                int col = n0 + 8 * bn + 2 * t4;
                float2 c0v = *(const float2*)&g_c0[col];
                int r1 = m0 + 16 * am + g;
                *(float2*)&sQK[r1 * QK_S + col] =
                    make_float2(acc[am][bn][0] + c0v.x, acc[am][bn][1] + c0v.y);
                *(float2*)&sQK[(r1 + 8) * QK_S + col] =
                    make_float2(acc[am][bn][2] + c0v.x, acc[am][bn][3] + c0v.y);
            }
        }
    }
    __syncthreads();

    // ---- Phase B: gather + local softmax + pooled feats + global path ----
    int idx0[8], idx1[8];
    #pragma unroll
    for (int r = 0; r < 8; ++r) {
        int eg = e0 + 8 * wid + r;
        int egc = eg < E_TOT ? eg : E_TOT - 1;
        idx0[r] = ei[egc];
        idx1[r] = ei[E_TOT + egc];
    }
    #pragma unroll 2
    for (int r = 0; r < 8; ++r) {
        int el = 8 * wid + r;
        int eg = e0 + el;
        if (eg < E_TOT) {
            const float4* srcp = (const float4*)(gf + (size_t)idx0[r] * 512);
            const float4* dstp = (const float4*)(gf + (size_t)idx1[r] * 512);
            float4 sv[4], dv[4];
            #pragma unroll
            for (int s2 = 0; s2 < 4; ++s2) {
                sv[s2] = srcp[s2 * 32 + lane];
                dv[s2] = dstp[s2 * 32 + lane];
            }

            // gather-independent work under the loads
            unsigned hu0 = sEAhi[el * EA_U + 2 * lane];
            unsigned hu1 = sEAhi[el * EA_U + 2 * lane + 1];
            unsigned lu0 = sEAlo[el * EA_U + 2 * lane];
            unsigned lu1 = sEAlo[el * EA_U + 2 * lane + 1];
            float2 hf0 = __bfloat1622float2(u_as_bf2(hu0));
            float2 hf1 = __bfloat1622float2(u_as_bf2(hu1));
            float2 lf0 = __bfloat1622float2(u_as_bf2(lu0));
            float2 lf1 = __bfloat1622float2(u_as_bf2(lu1));
            float4 eav = make_float4(hf0.x + lf0.x, hf0.y + lf0.y,
                                     hf1.x + lf1.x, hf1.y + lf1.y);
            float4 kq0 = ((const float4*)g_kqg)[4 * lane + 0];
            float4 kq1 = ((const float4*)g_kqg)[4 * lane + 1];
            float4 kq2 = ((const float4*)g_kqg)[4 * lane + 2];
            float4 kq3 = ((const float4*)g_kqg)[4 * lane + 3];
            float g0 = eav.x*kq0.x + eav.y*kq1.x + eav.z*kq2.x + eav.w*kq3.x;
            float g1 = eav.x*kq0.y + eav.y*kq1.y + eav.z*kq2.y + eav.w*kq3.y;
            float g2 = eav.x*kq0.z + eav.y*kq1.z + eav.z*kq2.z + eav.w*kq3.z;
            float g3 = eav.x*kq0.w + eav.y*kq1.w + eav.z*kq2.w + eav.w*kq3.w;
            float4 qlo = *(const float4*)&sQK[el * QK_S + 4 * lane];
            float4 qhi = *(const float4*)&sQK[el * QK_S + 128 + 4 * lane];

            float sc0 = dot4(qlo, sv[0]) + dot4(qhi, dv[0]);
            float sc1 = dot4(qlo, sv[1]) + dot4(qhi, dv[1]);
            float sc2 = dot4(qlo, sv[2]) + dot4(qhi, dv[2]);
            float sc3 = dot4(qlo, sv[3]) + dot4(qhi, dv[3]);

            // merged 8-value butterfly reduction
            #pragma unroll
            for (int o = 16; o > 0; o >>= 1) {
                sc0 += __shfl_xor_sync(0xFFFFFFFFu, sc0, o);
                sc1 += __shfl_xor_sync(0xFFFFFFFFu, sc1, o);
                sc2 += __shfl_xor_sync(0xFFFFFFFFu, sc2, o);
                sc3 += __shfl_xor_sync(0xFFFFFFFFu, sc3, o);
                g0  += __shfl_xor_sync(0xFFFFFFFFu, g0, o);
                g1  += __shfl_xor_sync(0xFFFFFFFFu, g1, o);
                g2  += __shfl_xor_sync(0xFFFFFFFFu, g2, o);
                g3  += __shfl_xor_sync(0xFFFFFFFFu, g3, o);
            }

            float z0 = sc0 * SCALE, z1 = sc1 * SCALE, z2 = sc2 * SCALE, z3 = sc3 * SCALE;
            float mz = fmaxf(fmaxf(z0, z1), fmaxf(z2, z3));
            float a0 = __expf(z0 - mz), a1 = __expf(z1 - mz);
            float a2 = __expf(z2 - mz), a3 = __expf(z3 - mz);
            float inv = 1.f / (a0 + a1 + a2 + a3);
            a0 *= inv; a1 *= inv; a2 *= inv; a3 *= inv;
            float4 plo, phi;
            plo.x = a0*sv[0].x + a1*sv[1].x + a2*sv[2].x + a3*sv[3].x;
            plo.y = a0*sv[0].y + a1*sv[1].y + a2*sv[2].y + a3*sv[3].y;
            plo.z = a0*sv[0].z + a1*sv[1].z + a2*sv[2].z + a3*sv[3].z;
            plo.w = a0*sv[0].w + a1*sv[1].w + a2*sv[2].w + a3*sv[3].w;
            phi.x = a0*dv[0].x + a1*dv[1].x + a2*dv[2].x + a3*dv[3].x;
            phi.y = a0*dv[0].y + a1*dv[1].y + a2*dv[2].y + a3*dv[3].y;
            phi.z = a0*dv[0].z + a1*dv[1].z + a2*dv[2].z + a3*dv[3].z;
            phi.w = a0*dv[0].w + a1*dv[1].w + a2*dv[2].w + a3*dv[3].w;
            *(float4*)&sQK[el * QK_S + 4 * lane] = plo;         // in-place pooled
            *(float4*)&sQK[el * QK_S + 128 + 4 * lane] = phi;

            float y0 = (g0 + g_cgs[0]) * SCALE, y1 = (g1 + g_cgs[1]) * SCALE;
            float y2 = (g2 + g_cgs[2]) * SCALE, y3 = (g3 + g_cgs[3]) * SCALE;
            float my = fmaxf(fmaxf(y0, y1), fmaxf(y2, y3));
            float b0 = __expf(y0 - my), b1 = __expf(y1 - my);
            float b2 = __expf(y2 - my), b3 = __expf(y3 - my);
            float binv = 1.f / (b0 + b1 + b2 + b3);
            b0 *= binv; b1 *= binv; b2 *= binv; b3 *= binv;
            if (lane == 0) {
                float* ap = attn_out + (size_t)eg * 4;
                ap[0] = b0; ap[1] = b1; ap[2] = b2; ap[3] = b3;
            }
            float4 m0v = ((const float4*)g_M)[lane];
            float4 m1v = ((const float4*)g_M)[32 + lane];
            float4 m2v = ((const float4*)g_M)[64 + lane];
            float4 m3v = ((const float4*)g_M)[96 + lane];
            float4 bo4 = ((const float4*)bo_g)[lane];
            float4 go;
            go.x = b0*m0v.x + b1*m1v.x + b2*m2v.x + b3*m3v.x + bo4.x;
            go.y = b0*m0v.y + b1*m1v.y + b2*m2v.y + b3*m3v.y + bo4.y;
            go.z = b0*m0v.z + b1*m1v.z + b2*m2v.z + b3*m3v.z + bo4.z;
            go.w = b0*m0v.w + b1*m1v.w + b2*m2v.w + b3*m3v.w + bo4.w;
            float* orow = out + (size_t)eg * 384;
            ((float4*)orow)[lane] = eav;
            ((float4*)(orow + 256))[lane] = go;
        }
    }
    __syncthreads();

    // ---- Phase C: local_out[64][128] = pooled @ W2^T + bias2 (bf16) ----
    {
        const int cm = wid >> 2;         // 0..1
        const int cn = wid & 3;          // 0..3
        const int m0 = cm * 32;
        const int n0 = cn * 32;
        float acc[2][4][4];
        #pragma unroll
        for (int am = 0; am < 2; ++am)
            #pragma unroll
            for (int bn = 0; bn < 4; ++bn)
                #pragma unroll
                for (int q = 0; q < 4; ++q) acc[am][bn][q] = 0.f;

        uint4 bp0[4], bp1[4];
        #pragma unroll
        for (int bn = 0; bn < 4; ++bn)
            bp0[bn] = __ldg(&g_W2b4[((n0 + 8 * bn + g) * 16 + 0) * 4 + t4]);

        #pragma unroll 1
        for (int kg = 0; kg < 16; kg += 2) {
            #pragma unroll
            for (int bn = 0; bn < 4; ++bn)
                bp1[bn] = __ldg(&g_W2b4[((n0 + 8 * bn + g) * 16 + kg + 1) * 4 + t4]);

            {
                unsigned Ah[2][4], Al[2][4];
                #pragma unroll
                for (int am = 0; am < 2; ++am) {
                    int R = m0 + 16 * am;
                    float2 p00 = *(const float2*)&sQK[(R + g)     * QK_S + kg * 16 + 2 * t4];
                    float2 p10 = *(const float2*)&sQK[(R + g + 8) * QK_S + kg * 16 + 2 * t4];
                    float2 p01 = *(const float2*)&sQK[(R + g)     * QK_S + kg * 16 + 2 * t4 + 8];
                    float2 p11 = *(const float2*)&sQK[(R + g + 8) * QK_S + kg * 16 + 2 * t4 + 8];
                    split_bf2(p00.x, p00.y, Ah[am][0], Al[am][0]);
                    split_bf2(p10.x, p10.y, Ah[am][1], Al[am][1]);
                    split_bf2(p01.x, p01.y, Ah[am][2], Al[am][2]);
                    split_bf2(p11.x, p11.y, Ah[am][3], Al[am][3]);
                }
                #pragma unroll
                for (int bn = 0; bn < 4; ++bn) {
                    #pragma unroll
                    for (int am = 0; am < 2; ++am) {
                        mma16(acc[am][bn], Ah[am], bp0[bn].x, bp0[bn].y);
                        mma16(acc[am][bn], Ah[am], bp0[bn].z, bp0[bn].w);
                        mma16(acc[am][bn], Al[am], bp0[bn].x, bp0[bn].y);
                    }
                }
            }

            if (kg + 2 < 16) {
                #pragma unroll
                for (int bn = 0; bn < 4; ++bn)
                    bp0[bn] = __ldg(&g_W2b4[((n0 + 8 * bn + g) * 16 + kg + 2) * 4 + t4]);
            }

            {
                unsigned Ah[2][4], Al[2][4];
                #pragma unroll
                for (int am = 0; am < 2; ++am) {
                    int R = m0 + 16 * am;
                    float2 p00 = *(const float2*)&sQK[(R + g)     * QK_S + (kg+1) * 16 + 2 * t4];
                    float2 p10 = *(const float2*)&sQK[(R + g + 8) * QK_S + (kg+1) * 16 + 2 * t4];
                    float2 p01 = *(const float2*)&sQK[(R + g)     * QK_S + (kg+1) * 16 + 2 * t4 + 8];
                    float2 p11 = *(const float2*)&sQK[(R + g + 8) * QK_S + (kg+1) * 16 + 2 * t4 + 8];
                    split_bf2(p00.x, p00.y, Ah[am][0], Al[am][0]);
                    split_bf2(p10.x, p10.y, Ah[am][1], Al[am][1]);
                    split_bf2(p01.x, p01.y, Ah[am][2], Al[am][2]);
                    split_bf2(p11.x, p11.y, Ah[am][3], Al[am][3]);
                }
                #pragma unroll
                for (int bn = 0; bn < 4; ++bn) {
                    #pragma unroll
                    for (int am = 0; am < 2; ++am) {
                        mma16(acc[am][bn], Ah[am], bp1[bn].x, bp1[bn].y);
                        mma16(acc[am][bn], Ah[am], bp1[bn].z, bp1[bn].w);
                        mma16(acc[am][bn], Al[am], bp1[bn].x, bp1[bn].y);
                    }
                }
            }
        }

        // epilogue: + bias2 -> out[:, 128:256]
        #pragma unroll
        for (int am = 0; am < 2; ++am) {
            #pragma unroll
            for (int bn = 0; bn < 4; ++bn) {
                int h = n0 + 8 * bn + 2 * t4;
                float2 bv = *(const float2*)&g_bias2[h];
                int e1 = e0 + m0 + 16 * am + g;
                if (e1 < E_TOT) {
                    *(float2*)&out[(size_t)e1 * 384 + 128 + h] =
                        make_float2(acc[am][bn][0] + bv.x, acc[am][bn][1] + bv.y);
                }
                int e2 = e1 + 8;
                if (e2 < E_TOT) {
                    *(float2*)&out[(size_t)e2 * 384 + 128 + h] =
                        make_float2(acc[am][bn][2] + bv.x, acc[am][bn][3] + bv.y);
                }
            }
        }
    }
}

// ---------------- launch ---------------------------------------------------
extern "C" void kernel_launch(void* const* d_in, const int* in_sizes, int n_in,
                              void* d_out, int out_size) {
    const float* ea   = (const float*)d_in[0];
    const float* gf   = (const float*)d_in[1];
    const int*   ei   = (const int*)d_in[2];
    const float* wq_l = (const float*)d_in[3];
    const float* wk_l = (const float*)d_in[4];
    const float* wv_l = (const float*)d_in[5];
    const float* bq_l = (const float*)d_in[6];
    const float* bv_l = (const float*)d_in[8];
    const float* wo_l = (const float*)d_in[9];
    const float* bo_l = (const float*)d_in[10];
    const float* wq_g = (const float*)d_in[11];
    const float* wk_g = (const float*)d_in[12];
    const float* wv_g = (const float*)d_in[13];
    const float* bq_g = (const float*)d_in[14];
    const float* bk_g = (const float*)d_in[15];
    const float* bv_g = (const float*)d_in[16];
    const float* wo_g = (const float*)d_in[17];
    const float* bo_g = (const float*)d_in[18];

    float* out        = (float*)d_out;
    float* out_pooled = out + (size_t)E_TOT * 384;
    float* out_attn   = out_pooled + 512;

    const int MAIN_SMEM = (2 * 64 * EA_U + 16640) * 4;   // 101376 B
    const int K2_SMEM   = 2 * 16896 * 4;                  // 135168 B

    cudaFuncSetAttribute(k1_precompute,
                         cudaFuncAttributeMaxDynamicSharedMemorySize, 67584);
    cudaFuncSetAttribute(k2_small,
                         cudaFuncAttributeMaxDynamicSharedMemorySize, K2_SMEM);
    cudaFuncSetAttribute(main_edge_kernel,
                         cudaFuncAttributeMaxDynamicSharedMemorySize, MAIN_SMEM);

    k1_precompute<<<POOL_BLKS + 386, 512, 67584>>>(gf, wq_l, wk_l, wv_l, wo_l,
                                                   bq_l, bv_l, bo_l);
    k2_small<<<1, 512, K2_SMEM>>>(wk_g, wv_g, wo_g, wq_g,
                                  bk_g, bv_g, bq_g, out_pooled);
    main_edge_kernel<<<GRID_MAIN, 256, MAIN_SMEM>>>(ea, gf, ei, bo_g, out, out_attn);
}

// round 14
// speedup vs baseline: 1.0313x; 1.0313x over previous
#include <cuda_runtime.h>
#include <cuda_bf16.h>

#define E_TOT   100000
#define NN      50000
#define POOL_BLKS 296
#define ROWS_PER_BLK 169
#define TILE_E  64
#define GRID_MAIN ((E_TOT + TILE_E - 1) / TILE_E)
#define EA_U    68      /* sEAhi/sEAlo row stride in uints (64 data + 4 pad) */
#define QK_S    260     /* sQK row stride (floats) */
#define SCALE   0.08838834764831845f   /* 1/sqrt(128) */

// ---------------- device scratch ----------------
__device__ float g_partial[POOL_BLKS * 512];
__device__ float g_pooled[512];
__device__ float g_kg[512];
__device__ float g_vg[512];
__device__ float g_M[512];          // [4][128] = v_g @ wo_g^T
__device__ float g_kqg[512];        // [128][4]
__device__ float g_cgs[4];
__device__ float g_c0[256];         // bq_l @ wk_l
__device__ float g_bias2[128];      // bv_l @ wo_l^T + bo_l
// B matrices pre-split to bf16 hi/lo in m16n8k16 fragment order:
__device__ uint4 g_Cb4[256 * 8 * 4];    // C:  n=256, k=128 (kg 0..7)
__device__ uint4 g_W2b4[128 * 16 * 4];  // W2: n=128, k=256 (kg 0..15)

__device__ __forceinline__ float dot4(float4 a, float4 b) {
    return a.x * b.x + a.y * b.y + a.z * b.z + a.w * b.w;
}

__device__ __forceinline__ void mma16(float* d, const unsigned* a, unsigned b0, unsigned b1) {
    asm volatile(
        "mma.sync.aligned.m16n8k16.row.col.f32.bf16.bf16.f32 "
        "{%0,%1,%2,%3}, {%4,%5,%6,%7}, {%8,%9}, {%0,%1,%2,%3};"
        : "+f"(d[0]), "+f"(d[1]), "+f"(d[2]), "+f"(d[3])
        : "r"(a[0]), "r"(a[1]), "r"(a[2]), "r"(a[3]), "r"(b0), "r"(b1));
}

__device__ __forceinline__ unsigned bf2_as_u(__nv_bfloat162 h) {
    return *(unsigned*)&h;
}
__device__ __forceinline__ __nv_bfloat162 u_as_bf2(unsigned u) {
    return *(__nv_bfloat162*)&u;
}

// split float pair -> hi bf16x2, lo bf16x2
__device__ __forceinline__ void split_bf2(float x, float y, unsigned& hi, unsigned& lo) {
    __nv_bfloat162 h = __float22bfloat162_rn(make_float2(x, y));
    float2 hf = __bfloat1622float2(h);
    __nv_bfloat162 l = __float22bfloat162_rn(make_float2(x - hf.x, y - hf.y));
    hi = bf2_as_u(h);
    lo = bf2_as_u(l);
}

// write one fp32 value as pre-split bf16 hi/lo into fragment-ordered array.
__device__ __forceinline__ void write_b_split(__nv_bfloat16* base, int n, int k,
                                              int kgs, float v) {
    int kg = k >> 4, r = k & 15;
    int word, t4;
    if (r < 8) { t4 = r >> 1; word = 0; }
    else       { t4 = (r - 8) >> 1; word = 1; }
    int half = r & 1;
    size_t bidx = ((((size_t)(n * kgs + kg) * 4 + t4) * 4 + word) * 2 + half);
    __nv_bfloat16 hi = __float2bfloat16(v);
    __nv_bfloat16 lo = __float2bfloat16(v - __bfloat162float(hi));
    base[bidx] = hi;
    base[bidx + 4] = lo;
}

// ---------------- kernel 1: pool partials + C + W2 + c0 + bias2 ----------
// blocks 0..295: pool partial (float4, 4 rows in flight);
// 296..423: C k-rows; 424..679: W2 k-cols; 680: c0; 681: bias2.
__global__ void k1_precompute(const float* __restrict__ gf,
                              const float* __restrict__ wq_l,
                              const float* __restrict__ wk_l,
                              const float* __restrict__ wv_l,
                              const float* __restrict__ wo_l,
                              const float* __restrict__ bq_l,
                              const float* __restrict__ bv_l,
                              const float* __restrict__ bo_l) {
    extern __shared__ float st[];
    int b = blockIdx.x, t = threadIdx.x;
    if (b < POOL_BLKS) {
        int r0 = b * ROWS_PER_BLK;
        int nrows = NN - r0;
        if (nrows > ROWS_PER_BLK) nrows = ROWS_PER_BLK;
        int tq = t & 127;          // float4 column group
        int tr = t >> 7;           // row offset 0..3
        const float4* p4 = (const float4*)gf;
        float4 a0 = make_float4(0.f, 0.f, 0.f, 0.f);
        float4 a1 = a0, a2 = a0, a3 = a0;
        for (int r = 0; r < nrows; r += 16) {
            int rr0 = r + tr;
            int rr1 = r + 4 + tr;
            int rr2 = r + 8 + tr;
            int rr3 = r + 12 + tr;
            if (rr0 < nrows) {
                float4 v = p4[(size_t)(r0 + rr0) * 128 + tq];
                a0.x += v.x; a0.y += v.y; a0.z += v.z; a0.w += v.w;
            }
            if (rr1 < nrows) {
                float4 v = p4[(size_t)(r0 + rr1) * 128 + tq];
                a1.x += v.x; a1.y += v.y; a1.z += v.z; a1.w += v.w;
            }
            if (rr2 < nrows) {
                float4 v = p4[(size_t)(r0 + rr2) * 128 + tq];
                a2.x += v.x; a2.y += v.y; a2.z += v.z; a2.w += v.w;
            }
            if (rr3 < nrows) {
                float4 v = p4[(size_t)(r0 + rr3) * 128 + tq];
                a3.x += v.x; a3.y += v.y; a3.z += v.z; a3.w += v.w;
            }
        }
        float4 acc = make_float4((a0.x + a1.x) + (a2.x + a3.x),
                                 (a0.y + a1.y) + (a2.y + a3.y),
                                 (a0.z + a1.z) + (a2.z + a3.z),
                                 (a0.w + a1.w) + (a2.w + a3.w));
        float4* st4 = (float4*)st;
        st4[tr * 128 + tq] = acc;
        __syncthreads();
        if (t < 128) {
            float4 s0 = st4[t], s1 = st4[128 + t], s2 = st4[256 + t], s3 = st4[384 + t];
            float4 s = make_float4((s0.x + s1.x) + (s2.x + s3.x),
                                   (s0.y + s1.y) + (s2.y + s3.y),
                                   (s0.z + s1.z) + (s2.z + s3.z),
                                   (s0.w + s1.w) + (s2.w + s3.w));
            ((float4*)g_partial)[b * 128 + t] = s;
        }
    } else if (b < POOL_BLKS + 128) {
        int i = b - POOL_BLKS;      // C k-row 0..127
        if (t < 256) {
            float a = 0.f;
            for (int h = 0; h < 128; ++h)
                a += __ldg(&wq_l[h * 128 + i]) * wk_l[h * 256 + t];
            write_b_split((__nv_bfloat16*)g_Cb4, t, i, 8, a);
        }
    } else if (b < POOL_BLKS + 384) {
        int j = b - (POOL_BLKS + 128);   // W2 k-index 0..255
        for (int idx = t; idx < 16384; idx += 512) {
            int h = idx >> 7, m = idx & 127;
            st[m * 132 + h] = wo_l[idx];
        }
        __syncthreads();
        if (t < 128) {
            float a = 0.f;
            for (int m = 0; m < 128; ++m)
                a += __ldg(&wv_l[m * 256 + j]) * st[m * 132 + t];
            write_b_split((__nv_bfloat16*)g_W2b4, t, j, 16, a);
        }
    } else if (b == POOL_BLKS + 384) {
        if (t < 256) {
            float a = 0.f;
            for (int h = 0; h < 128; ++h) a += bq_l[h] * wk_l[h * 256 + t];
            g_c0[t] = a;
        }
    } else {
        for (int idx = t; idx < 16384; idx += 512) {
            int h = idx >> 7, m = idx & 127;
            st[m * 132 + h] = wo_l[idx];
        }
        __syncthreads();
        if (t < 128) {
            float a = 0.f;
            for (int m = 0; m < 128; ++m) a += bv_l[m] * st[m * 132 + t];
            g_bias2[t] = a + bo_l[t];
        }
    }
}

// ---------------- kernel 2: pooled + global-path small matrices ----------
// Fused staging: {wk_g, wv_g} -> {k_g, v_g}; then {wo_g, wq_g} -> {M, kqg, cgs}.
// Reduction over pool partials uses 8 independent accumulators (MLP=8).
__global__ void k2_small(const float* __restrict__ wk_g,
                         const float* __restrict__ wv_g,
                         const float* __restrict__ wo_g,
                         const float* __restrict__ wq_g,
                         const float* __restrict__ bk_g,
                         const float* __restrict__ bv_g,
                         const float* __restrict__ bq_g,
                         float* __restrict__ out_pooled) {
    extern __shared__ float st[];       // 2 x 16896 floats
    float* st2 = st + 16896;
    int t = threadIdx.x;

    // 8-way independent accumulation (POOL_BLKS = 296 = 8*37)
    {
        float s0 = 0.f, s1 = 0.f, s2 = 0.f, s3 = 0.f;
        float s4 = 0.f, s5 = 0.f, s6 = 0.f, s7 = 0.f;
        #pragma unroll 1
        for (int b = 0; b < POOL_BLKS; b += 8) {
            s0 += g_partial[(b + 0) * 512 + t];
            s1 += g_partial[(b + 1) * 512 + t];
            s2 += g_partial[(b + 2) * 512 + t];
            s3 += g_partial[(b + 3) * 512 + t];
            s4 += g_partial[(b + 4) * 512 + t];
            s5 += g_partial[(b + 5) * 512 + t];
            s6 += g_partial[(b + 6) * 512 + t];
            s7 += g_partial[(b + 7) * 512 + t];
        }
        float s = ((s0 + s1) + (s2 + s3)) + ((s4 + s5) + (s6 + s7));
        s *= (1.0f / NN);
        g_pooled[t] = s;
        out_pooled[t] = s;
    }

    // stage wk_g and wv_g together (transposed)
    for (int idx = t; idx < 16384; idx += 512) {
        int h = idx >> 7, j = idx & 127;
        st[j * 132 + h]  = wk_g[idx];
        st2[j * 132 + h] = wv_g[idx];
    }
    __syncthreads();
    {
        int si = t >> 7, h = t & 127;
        float a = 0.f, a2 = 0.f;
        for (int j = 0; j < 128; ++j) {
            float p = g_pooled[si * 128 + j];
            a  += p * st[j * 132 + h];
            a2 += p * st2[j * 132 + h];
        }
        g_kg[t] = a + bk_g[h];
        g_vg[t] = a2 + bv_g[h];
    }
    __syncthreads();

    // stage wo_g and wq_g together (transposed)
    for (int idx = t; idx < 16384; idx += 512) {
        int h = idx >> 7, m = idx & 127;
        st[m * 132 + h]  = wo_g[idx];
        st2[m * 132 + h] = wq_g[idx];
    }
    __syncthreads();
    {
        int si = t >> 7, h = t & 127;
        float a = 0.f;
        for (int m = 0; m < 128; ++m) a += g_vg[si * 128 + m] * st[m * 132 + h];
        g_M[t] = a;
    }
    {
        int i = t >> 2, si = t & 3;
        float a = 0.f;
        for (int h = 0; h < 128; ++h) a += st2[i * 132 + h] * g_kg[si * 128 + h];
        g_kqg[i * 4 + si] = a;
    }
    if (t < 4) {
        float a = 0.f;
        for (int h = 0; h < 128; ++h) a += bq_g[h] * g_kg[t * 128 + h];
        g_cgs[t] = a;
    }
}

// ---------------- kernel 3: fused per-edge kernel (256 thr, 2 CTA/SM) ----
// (R9 main kernel verbatim — measured 239.1 us)
__global__ void __launch_bounds__(256, 2)
main_edge_kernel(const float* __restrict__ ea_g,
                 const float* __restrict__ gf,
                 const int* __restrict__ ei,
                 const float* __restrict__ bo_g,
                 float* __restrict__ out,
                 float* __restrict__ attn_out) {
    extern __shared__ float smem[];
    unsigned* sEAhi = (unsigned*)smem;            // 64*68 uints
    unsigned* sEAlo = sEAhi + 64 * EA_U;          // 64*68 uints
    float*    sQK   = smem + 2 * 64 * EA_U;       // 64*260 floats
    const int tid  = threadIdx.x;
    const int wid  = tid >> 5;    // 0..7
    const int lane = tid & 31;
    const int g    = lane >> 2;   // 0..7
    const int t4   = lane & 3;    // 0..3
    const int e0   = blockIdx.x * TILE_E;

    // stage edge_attr tile pre-split to bf16 hi/lo (zero-fill OOB rows)
    for (int idx = tid; idx < 2048; idx += 256) {
        int r = idx >> 5, c = idx & 31;          // c: float4 col (k = 4c)
        float4 v = make_float4(0.f, 0.f, 0.f, 0.f);
        if (e0 + r < E_TOT) v = ((const float4*)ea_g)[(size_t)(e0 + r) * 32 + c];
        unsigned h0, l0, h1, l1;
        split_bf2(v.x, v.y, h0, l0);
        split_bf2(v.z, v.w, h1, l1);
        sEAhi[r * EA_U + 2 * c]     = h0;
        sEAhi[r * EA_U + 2 * c + 1] = h1;
        sEAlo[r * EA_U + 2 * c]     = l0;
        sEAlo[r * EA_U + 2 * c + 1] = l1;
    }
    __syncthreads();

    // ---- Phase A: qk[64][256] = ea @ C + c0 (bf16 m16n8k16, 3-term) ----
    {
        const int wm = wid >> 2;          // 0..1
        const int wn = wid & 3;           // 0..3
        const int m0 = wm * 32;
        const int n0 = wn * 64;
        float acc[2][8][4];
        #pragma unroll
        for (int am = 0; am < 2; ++am)
            #pragma unroll
            for (int bn = 0; bn < 8; ++bn)
                #pragma unroll
                for (int q = 0; q < 4; ++q) acc[am][bn][q] = 0.f;

        uint4 bpc[4], bpn[4];
        #pragma unroll
        for (int b2 = 0; b2 < 4; ++b2)
            bpc[b2] = __ldg(&g_Cb4[((n0 + 8 * b2 + g) * 8 + 0) * 4 + t4]);

        #pragma unroll 1
        for (int kg = 0; kg < 8; ++kg) {
            unsigned Ah[2][4], Al[2][4];
            #pragma unroll
            for (int am = 0; am < 2; ++am) {
                int R = m0 + 16 * am;
                Ah[am][0] = sEAhi[(R + g)     * EA_U + kg * 8 + t4];
                Ah[am][1] = sEAhi[(R + g + 8) * EA_U + kg * 8 + t4];
                Ah[am][2] = sEAhi[(R + g)     * EA_U + kg * 8 + 4 + t4];
                Ah[am][3] = sEAhi[(R + g + 8) * EA_U + kg * 8 + 4 + t4];
                Al[am][0] = sEAlo[(R + g)     * EA_U + kg * 8 + t4];
                Al[am][1] = sEAlo[(R + g + 8) * EA_U + kg * 8 + t4];
                Al[am][2] = sEAlo[(R + g)     * EA_U + kg * 8 + 4 + t4];
                Al[am][3] = sEAlo[(R + g + 8) * EA_U + kg * 8 + 4 + t4];
            }
            #pragma unroll
            for (int b2 = 0; b2 < 4; ++b2)
                bpn[b2] = __ldg(&g_Cb4[((n0 + 32 + 8 * b2 + g) * 8 + kg) * 4 + t4]);
            #pragma unroll
            for (int b2 = 0; b2 < 4; ++b2) {
                #pragma unroll
                for (int am = 0; am < 2; ++am) {
                    mma16(acc[am][b2], Ah[am], bpc[b2].x, bpc[b2].y);
                    mma16(acc[am][b2], Ah[am], bpc[b2].z, bpc[b2].w);
                    mma16(acc[am][b2], Al[am], bpc[b2].x, bpc[b2].y);
                }
            }
            if (kg < 7) {
                #pragma unroll
                for (int b2 = 0; b2 < 4; ++b2)
                    bpc[b2] = __ldg(&g_Cb4[((n0 + 8 * b2 + g) * 8 + kg + 1) * 4 + t4]);
            }
            #pragma unroll
            for (int b2 = 0; b2 < 4; ++b2) {
                #pragma unroll
                for (int am = 0; am < 2; ++am) {
                    mma16(acc[am][4 + b2], Ah[am], bpn[b2].x, bpn[b2].y);
                    mma16(acc[am][4 + b2], Ah[am], bpn[b2].z, bpn[b2].w);
                    mma16(acc[am][4 + b2], Al[am], bpn[b2].x, bpn[b2].y);
                }
            }
        }

        // epilogue: qk + c0 -> sQK
        #pragma unroll
        for (int am = 0; am < 2; ++am) {
            #pragma unroll
            for (int bn = 0; bn < 8; ++bn) {
                int col = n0 + 8 * bn + 2 * t4;
                float2 c0v = *(const float2*)&g_c0[col];
                int r1 = m0 + 16 * am + g;
                *(float2*)&sQK[r1 * QK_S + col] =
                    make_float2(acc[am][bn][0] + c0v.x, acc[am][bn][1] + c0v.y);
                *(float2*)&sQK[(r1 + 8) * QK_S + col] =
                    make_float2(acc[am][bn][2] + c0v.x, acc[am][bn][3] + c0v.y);
            }
        }
    }
    __syncthreads();

    // ---- Phase B: gather + local softmax + pooled feats + global path ----
    int idx0[8], idx1[8];
    #pragma unroll
    for (int r = 0; r < 8; ++r) {
        int eg = e0 + 8 * wid + r;
        int egc = eg < E_TOT ? eg : E_TOT - 1;
        idx0[r] = ei[egc];
        idx1[r] = ei[E_TOT + egc];
    }
    #pragma unroll 2
    for (int r = 0; r < 8; ++r) {
        int el = 8 * wid + r;
        int eg = e0 + el;
        if (eg < E_TOT) {
            const float4* srcp = (const float4*)(gf + (size_t)idx0[r] * 512);
            const float4* dstp = (const float4*)(gf + (size_t)idx1[r] * 512);
            float4 sv[4], dv[4];
            #pragma unroll
            for (int s2 = 0; s2 < 4; ++s2) {
                sv[s2] = srcp[s2 * 32 + lane];
                dv[s2] = dstp[s2 * 32 + lane];
            }

            // gather-independent work under the loads
            unsigned hu0 = sEAhi[el * EA_U + 2 * lane];
            unsigned hu1 = sEAhi[el * EA_U + 2 * lane + 1];
            unsigned lu0 = sEAlo[el * EA_U + 2 * lane];
            unsigned lu1 = sEAlo[el * EA_U + 2 * lane + 1];
            float2 hf0 = __bfloat1622float2(u_as_bf2(hu0));
            float2 hf1 = __bfloat1622float2(u_as_bf2(hu1));
            float2 lf0 = __bfloat1622float2(u_as_bf2(lu0));
            float2 lf1 = __bfloat1622float2(u_as_bf2(lu1));
            float4 eav = make_float4(hf0.x + lf0.x, hf0.y + lf0.y,
                                     hf1.x + lf1.x, hf1.y + lf1.y);
            float4 kq0 = ((const float4*)g_kqg)[4 * lane + 0];
            float4 kq1 = ((const float4*)g_kqg)[4 * lane + 1];
            float4 kq2 = ((const float4*)g_kqg)[4 * lane + 2];
            float4 kq3 = ((const float4*)g_kqg)[4 * lane + 3];
            float g0 = eav.x*kq0.x + eav.y*kq1.x + eav.z*kq2.x + eav.w*kq3.x;
            float g1 = eav.x*kq0.y + eav.y*kq1.y + eav.z*kq2.y + eav.w*kq3.y;
            float g2 = eav.x*kq0.z + eav.y*kq1.z + eav.z*kq2.z + eav.w*kq3.z;
            float g3 = eav.x*kq0.w + eav.y*kq1.w + eav.z*kq2.w + eav.w*kq3.w;
            float4 qlo = *(const float4*)&sQK[el * QK_S + 4 * lane];
            float4 qhi = *(const float4*)&sQK[el * QK_S + 128 + 4 * lane];

            float sc0 = dot4(qlo, sv[0]) + dot4(qhi, dv[0]);
            float sc1 = dot4(qlo, sv[1]) + dot4(qhi, dv[1]);
            float sc2 = dot4(qlo, sv[2]) + dot4(qhi, dv[2]);
            float sc3 = dot4(qlo, sv[3]) + dot4(qhi, dv[3]);

            // merged 8-value butterfly reduction
            #pragma unroll
            for (int o = 16; o > 0; o >>= 1) {
                sc0 += __shfl_xor_sync(0xFFFFFFFFu, sc0, o);
                sc1 += __shfl_xor_sync(0xFFFFFFFFu, sc1, o);
                sc2 += __shfl_xor_sync(0xFFFFFFFFu, sc2, o);
                sc3 += __shfl_xor_sync(0xFFFFFFFFu, sc3, o);
                g0  += __shfl_xor_sync(0xFFFFFFFFu, g0, o);
                g1  += __shfl_xor_sync(0xFFFFFFFFu, g1, o);
                g2  += __shfl_xor_sync(0xFFFFFFFFu, g2, o);
                g3  += __shfl_xor_sync(0xFFFFFFFFu, g3, o);
            }

            float z0 = sc0 * SCALE, z1 = sc1 * SCALE, z2 = sc2 * SCALE, z3 = sc3 * SCALE;
            float mz = fmaxf(fmaxf(z0, z1), fmaxf(z2, z3));
            float a0 = __expf(z0 - mz), a1 = __expf(z1 - mz);
            float a2 = __expf(z2 - mz), a3 = __expf(z3 - mz);
            float inv = 1.f / (a0 + a1 + a2 + a3);
            a0 *= inv; a1 *= inv; a2 *= inv; a3 *= inv;
            float4 plo, phi;
            plo.x = a0*sv[0].x + a1*sv[1].x + a2*sv[2].x + a3*sv[3].x;
            plo.y = a0*sv[0].y + a1*sv[1].y + a2*sv[2].y + a3*sv[3].y;
            plo.z = a0*sv[0].z + a1*sv[1].z + a2*sv[2].z + a3*sv[3].z;
            plo.w = a0*sv[0].w + a1*sv[1].w + a2*sv[2].w + a3*sv[3].w;
            phi.x = a0*dv[0].x + a1*dv[1].x + a2*dv[2].x + a3*dv[3].x;
            phi.y = a0*dv[0].y + a1*dv[1].y + a2*dv[2].y + a3*dv[3].y;
            phi.z = a0*dv[0].z + a1*dv[1].z + a2*dv[2].z + a3*dv[3].z;
            phi.w = a0*dv[0].w + a1*dv[1].w + a2*dv[2].w + a3*dv[3].w;
            *(float4*)&sQK[el * QK_S + 4 * lane] = plo;         // in-place pooled
            *(float4*)&sQK[el * QK_S + 128 + 4 * lane] = phi;

            float y0 = (g0 + g_cgs[0]) * SCALE, y1 = (g1 + g_cgs[1]) * SCALE;
            float y2 = (g2 + g_cgs[2]) * SCALE, y3 = (g3 + g_cgs[3]) * SCALE;
            float my = fmaxf(fmaxf(y0, y1), fmaxf(y2, y3));
            float b0 = __expf(y0 - my), b1 = __expf(y1 - my);
            float b2 = __expf(y2 - my), b3 = __expf(y3 - my);
            float binv = 1.f / (b0 + b1 + b2 + b3);
            b0 *= binv; b1 *= binv; b2 *= binv; b3 *= binv;
            if (lane == 0) {
                float* ap = attn_out + (size_t)eg * 4;
                ap[0] = b0; ap[1] = b1; ap[2] = b2; ap[3] = b3;
            }
            float4 m0v = ((const float4*)g_M)[lane];
            float4 m1v = ((const float4*)g_M)[32 + lane];
            float4 m2v = ((const float4*)g_M)[64 + lane];
            float4 m3v = ((const float4*)g_M)[96 + lane];
            float4 bo4 = ((const float4*)bo_g)[lane];
            float4 go;
            go.x = b0*m0v.x + b1*m1v.x + b2*m2v.x + b3*m3v.x + bo4.x;
            go.y = b0*m0v.y + b1*m1v.y + b2*m2v.y + b3*m3v.y + bo4.y;
            go.z = b0*m0v.z + b1*m1v.z + b2*m2v.z + b3*m3v.z + bo4.z;
            go.w = b0*m0v.w + b1*m1v.w + b2*m2v.w + b3*m3v.w + bo4.w;
            float* orow = out + (size_t)eg * 384;
            ((float4*)orow)[lane] = eav;
            ((float4*)(orow + 256))[lane] = go;
        }
    }
    __syncthreads();

    // ---- Phase C: local_out[64][128] = pooled @ W2^T + bias2 (bf16) ----
    {
        const int cm = wid >> 2;         // 0..1
        const int cn = wid & 3;          // 0..3
        const int m0 = cm * 32;
        const int n0 = cn * 32;
        float acc[2][4][4];
        #pragma unroll
        for (int am = 0; am < 2; ++am)
            #pragma unroll
            for (int bn = 0; bn < 4; ++bn)
                #pragma unroll
                for (int q = 0; q < 4; ++q) acc[am][bn][q] = 0.f;

        uint4 bp0[4], bp1[4];
        #pragma unroll
        for (int bn = 0; bn < 4; ++bn)
            bp0[bn] = __ldg(&g_W2b4[((n0 + 8 * bn + g) * 16 + 0) * 4 + t4]);

        #pragma unroll 1
        for (int kg = 0; kg < 16; kg += 2) {
            #pragma unroll
            for (int bn = 0; bn < 4; ++bn)
                bp1[bn] = __ldg(&g_W2b4[((n0 + 8 * bn + g) * 16 + kg + 1) * 4 + t4]);

            {
                unsigned Ah[2][4], Al[2][4];
                #pragma unroll
                for (int am = 0; am < 2; ++am) {
                    int R = m0 + 16 * am;
                    float2 p00 = *(const float2*)&sQK[(R + g)     * QK_S + kg * 16 + 2 * t4];
                    float2 p10 = *(const float2*)&sQK[(R + g + 8) * QK_S + kg * 16 + 2 * t4];
                    float2 p01 = *(const float2*)&sQK[(R + g)     * QK_S + kg * 16 + 2 * t4 + 8];
                    float2 p11 = *(const float2*)&sQK[(R + g + 8) * QK_S + kg * 16 + 2 * t4 + 8];
                    split_bf2(p00.x, p00.y, Ah[am][0], Al[am][0]);
                    split_bf2(p10.x, p10.y, Ah[am][1], Al[am][1]);
                    split_bf2(p01.x, p01.y, Ah[am][2], Al[am][2]);
                    split_bf2(p11.x, p11.y, Ah[am][3], Al[am][3]);
                }
                #pragma unroll
                for (int bn = 0; bn < 4; ++bn) {
                    #pragma unroll
                    for (int am = 0; am < 2; ++am) {
                        mma16(acc[am][bn], Ah[am], bp0[bn].x, bp0[bn].y);
                        mma16(acc[am][bn], Ah[am], bp0[bn].z, bp0[bn].w);
                        mma16(acc[am][bn], Al[am], bp0[bn].x, bp0[bn].y);
                    }
                }
            }

            if (kg + 2 < 16) {
                #pragma unroll
                for (int bn = 0; bn < 4; ++bn)
                    bp0[bn] = __ldg(&g_W2b4[((n0 + 8 * bn + g) * 16 + kg + 2) * 4 + t4]);
            }

            {
                unsigned Ah[2][4], Al[2][4];
                #pragma unroll
                for (int am = 0; am < 2; ++am) {
                    int R = m0 + 16 * am;
                    float2 p00 = *(const float2*)&sQK[(R + g)     * QK_S + (kg+1) * 16 + 2 * t4];
                    float2 p10 = *(const float2*)&sQK[(R + g + 8) * QK_S + (kg+1) * 16 + 2 * t4];
                    float2 p01 = *(const float2*)&sQK[(R + g)     * QK_S + (kg+1) * 16 + 2 * t4 + 8];
                    float2 p11 = *(const float2*)&sQK[(R + g + 8) * QK_S + (kg+1) * 16 + 2 * t4 + 8];
                    split_bf2(p00.x, p00.y, Ah[am][0], Al[am][0]);
                    split_bf2(p10.x, p10.y, Ah[am][1], Al[am][1]);
                    split_bf2(p01.x, p01.y, Ah[am][2], Al[am][2]);
                    split_bf2(p11.x, p11.y, Ah[am][3], Al[am][3]);
                }
                #pragma unroll
                for (int bn = 0; bn < 4; ++bn) {
                    #pragma unroll
                    for (int am = 0; am < 2; ++am) {
                        mma16(acc[am][bn], Ah[am], bp1[bn].x, bp1[bn].y);
                        mma16(acc[am][bn], Ah[am], bp1[bn].z, bp1[bn].w);
                        mma16(acc[am][bn], Al[am], bp1[bn].x, bp1[bn].y);
                    }
                }
            }
        }

        // epilogue: + bias2 -> out[:, 128:256]
        #pragma unroll
        for (int am = 0; am < 2; ++am) {
            #pragma unroll
            for (int bn = 0; bn < 4; ++bn) {
                int h = n0 + 8 * bn + 2 * t4;
                float2 bv = *(const float2*)&g_bias2[h];
                int e1 = e0 + m0 + 16 * am + g;
                if (e1 < E_TOT) {
                    *(float2*)&out[(size_t)e1 * 384 + 128 + h] =
                        make_float2(acc[am][bn][0] + bv.x, acc[am][bn][1] + bv.y);
                }
                int e2 = e1 + 8;
                if (e2 < E_TOT) {
                    *(float2*)&out[(size_t)e2 * 384 + 128 + h] =
                        make_float2(acc[am][bn][2] + bv.x, acc[am][bn][3] + bv.y);
                }
            }
        }
    }
}

// ---------------- launch ---------------------------------------------------
extern "C" void kernel_launch(void* const* d_in, const int* in_sizes, int n_in,
                              void* d_out, int out_size) {
    const float* ea   = (const float*)d_in[0];
    const float* gf   = (const float*)d_in[1];
    const int*   ei   = (const int*)d_in[2];
    const float* wq_l = (const float*)d_in[3];
    const float* wk_l = (const float*)d_in[4];
    const float* wv_l = (const float*)d_in[5];
    const float* bq_l = (const float*)d_in[6];
    const float* bv_l = (const float*)d_in[8];
    const float* wo_l = (const float*)d_in[9];
    const float* bo_l = (const float*)d_in[10];
    const float* wq_g = (const float*)d_in[11];
    const float* wk_g = (const float*)d_in[12];
    const float* wv_g = (const float*)d_in[13];
    const float* bq_g = (const float*)d_in[14];
    const float* bk_g = (const float*)d_in[15];
    const float* bv_g = (const float*)d_in[16];
    const float* wo_g = (const float*)d_in[17];
    const float* bo_g = (const float*)d_in[18];

    float* out        = (float*)d_out;
    float* out_pooled = out + (size_t)E_TOT * 384;
    float* out_attn   = out_pooled + 512;

    const int MAIN_SMEM = (2 * 64 * EA_U + 16640) * 4;   // 101376 B
    const int K2_SMEM   = 2 * 16896 * 4;                  // 135168 B

    cudaFuncSetAttribute(k1_precompute,
                         cudaFuncAttributeMaxDynamicSharedMemorySize, 67584);
    cudaFuncSetAttribute(k2_small,
                         cudaFuncAttributeMaxDynamicSharedMemorySize, K2_SMEM);
    cudaFuncSetAttribute(main_edge_kernel,
                         cudaFuncAttributeMaxDynamicSharedMemorySize, MAIN_SMEM);

    k1_precompute<<<POOL_BLKS + 386, 512, 67584>>>(gf, wq_l, wk_l, wv_l, wo_l,
                                                   bq_l, bv_l, bo_l);
    k2_small<<<1, 512, K2_SMEM>>>(wk_g, wv_g, wo_g, wq_g,
                                  bk_g, bv_g, bq_g, out_pooled);
    main_edge_kernel<<<GRID_MAIN, 256, MAIN_SMEM>>>(ea, gf, ei, bo_g, out, out_attn);
}

// round 15
// speedup vs baseline: 1.0400x; 1.0084x over previous
#include <cuda_runtime.h>
#include <cuda_bf16.h>

#define E_TOT   100000
#define NN      50000
#define POOL_BLKS 296
#define ROWS_PER_BLK 169
#define POOL2_BLKS 37          /* 296 / 8 */
#define TILE_E  64
#define GRID_MAIN ((E_TOT + TILE_E - 1) / TILE_E)
#define EA_U    68      /* sEAhi/sEAlo row stride in uints (64 data + 4 pad) */
#define QK_S    260     /* sQK row stride (floats) */
#define SCALE   0.08838834764831845f   /* 1/sqrt(128) */

// ---------------- device scratch ----------------
__device__ float g_partial[POOL_BLKS * 512];
__device__ float g_partial2[POOL2_BLKS * 512];
__device__ float g_pooled[512];
__device__ float g_kg[512];
__device__ float g_vg[512];
__device__ float g_M[512];          // [4][128] = v_g @ wo_g^T
__device__ float g_kqg[512];        // [128][4]
__device__ float g_cgs[4];
__device__ float g_c0[256];         // bq_l @ wk_l
__device__ float g_bias2[128];      // bv_l @ wo_l^T + bo_l
// B matrices pre-split to bf16 hi/lo in m16n8k16 fragment order:
__device__ uint4 g_Cb4[256 * 8 * 4];    // C:  n=256, k=128 (kg 0..7)
__device__ uint4 g_W2b4[128 * 16 * 4];  // W2: n=128, k=256 (kg 0..15)

__device__ __forceinline__ float dot4(float4 a, float4 b) {
    return a.x * b.x + a.y * b.y + a.z * b.z + a.w * b.w;
}

__device__ __forceinline__ void mma16(float* d, const unsigned* a, unsigned b0, unsigned b1) {
    asm volatile(
        "mma.sync.aligned.m16n8k16.row.col.f32.bf16.bf16.f32 "
        "{%0,%1,%2,%3}, {%4,%5,%6,%7}, {%8,%9}, {%0,%1,%2,%3};"
        : "+f"(d[0]), "+f"(d[1]), "+f"(d[2]), "+f"(d[3])
        : "r"(a[0]), "r"(a[1]), "r"(a[2]), "r"(a[3]), "r"(b0), "r"(b1));
}

// ldmatrix x4: loads a full m16k16 bf16 A fragment (4 regs) from shared memory.
__device__ __forceinline__ void ldsm_x4(unsigned* r, unsigned saddr) {
    asm volatile(
        "ldmatrix.sync.aligned.m8n8.x4.shared.b16 {%0,%1,%2,%3}, [%4];"
        : "=r"(r[0]), "=r"(r[1]), "=r"(r[2]), "=r"(r[3]) : "r"(saddr));
}

__device__ __forceinline__ unsigned bf2_as_u(__nv_bfloat162 h) {
    return *(unsigned*)&h;
}
__device__ __forceinline__ __nv_bfloat162 u_as_bf2(unsigned u) {
    return *(__nv_bfloat162*)&u;
}

// split float pair -> hi bf16x2, lo bf16x2
__device__ __forceinline__ void split_bf2(float x, float y, unsigned& hi, unsigned& lo) {
    __nv_bfloat162 h = __float22bfloat162_rn(make_float2(x, y));
    float2 hf = __bfloat1622float2(h);
    __nv_bfloat162 l = __float22bfloat162_rn(make_float2(x - hf.x, y - hf.y));
    hi = bf2_as_u(h);
    lo = bf2_as_u(l);
}

// write one fp32 value as pre-split bf16 hi/lo into fragment-ordered array.
__device__ __forceinline__ void write_b_split(__nv_bfloat16* base, int n, int k,
                                              int kgs, float v) {
    int kg = k >> 4, r = k & 15;
    int word, t4;
    if (r < 8) { t4 = r >> 1; word = 0; }
    else       { t4 = (r - 8) >> 1; word = 1; }
    int half = r & 1;
    size_t bidx = ((((size_t)(n * kgs + kg) * 4 + t4) * 4 + word) * 2 + half);
    __nv_bfloat16 hi = __float2bfloat16(v);
    __nv_bfloat16 lo = __float2bfloat16(v - __bfloat162float(hi));
    base[bidx] = hi;
    base[bidx + 4] = lo;
}

// ---------------- kernel 1: pool partials + C + W2 + c0 + bias2 ----------
// blocks 0..295: pool partial (float4, 4 rows in flight);
// 296..423: C k-rows; 424..679: W2 k-cols; 680: c0; 681: bias2.
__global__ void k1_precompute(const float* __restrict__ gf,
                              const float* __restrict__ wq_l,
                              const float* __restrict__ wk_l,
                              const float* __restrict__ wv_l,
                              const float* __restrict__ wo_l,
                              const float* __restrict__ bq_l,
                              const float* __restrict__ bv_l,
                              const float* __restrict__ bo_l) {
    extern __shared__ float st[];
    int b = blockIdx.x, t = threadIdx.x;
    if (b < POOL_BLKS) {
        int r0 = b * ROWS_PER_BLK;
        int nrows = NN - r0;
        if (nrows > ROWS_PER_BLK) nrows = ROWS_PER_BLK;
        int tq = t & 127;          // float4 column group
        int tr = t >> 7;           // row offset 0..3
        const float4* p4 = (const float4*)gf;
        float4 a0 = make_float4(0.f, 0.f, 0.f, 0.f);
        float4 a1 = a0, a2 = a0, a3 = a0;
        for (int r = 0; r < nrows; r += 16) {
            int rr0 = r + tr;
            int rr1 = r + 4 + tr;
            int rr2 = r + 8 + tr;
            int rr3 = r + 12 + tr;
            if (rr0 < nrows) {
                float4 v = p4[(size_t)(r0 + rr0) * 128 + tq];
                a0.x += v.x; a0.y += v.y; a0.z += v.z; a0.w += v.w;
            }
            if (rr1 < nrows) {
                float4 v = p4[(size_t)(r0 + rr1) * 128 + tq];
                a1.x += v.x; a1.y += v.y; a1.z += v.z; a1.w += v.w;
            }
            if (rr2 < nrows) {
                float4 v = p4[(size_t)(r0 + rr2) * 128 + tq];
                a2.x += v.x; a2.y += v.y; a2.z += v.z; a2.w += v.w;
            }
            if (rr3 < nrows) {
                float4 v = p4[(size_t)(r0 + rr3) * 128 + tq];
                a3.x += v.x; a3.y += v.y; a3.z += v.z; a3.w += v.w;
            }
        }
        float4 acc = make_float4((a0.x + a1.x) + (a2.x + a3.x),
                                 (a0.y + a1.y) + (a2.y + a3.y),
                                 (a0.z + a1.z) + (a2.z + a3.z),
                                 (a0.w + a1.w) + (a2.w + a3.w));
        float4* st4 = (float4*)st;
        st4[tr * 128 + tq] = acc;
        __syncthreads();
        if (t < 128) {
            float4 s0 = st4[t], s1 = st4[128 + t], s2 = st4[256 + t], s3 = st4[384 + t];
            float4 s = make_float4((s0.x + s1.x) + (s2.x + s3.x),
                                   (s0.y + s1.y) + (s2.y + s3.y),
                                   (s0.z + s1.z) + (s2.z + s3.z),
                                   (s0.w + s1.w) + (s2.w + s3.w));
            ((float4*)g_partial)[b * 128 + t] = s;
        }
    } else if (b < POOL_BLKS + 128) {
        int i = b - POOL_BLKS;      // C k-row 0..127
        if (t < 256) {
            float a = 0.f;
            for (int h = 0; h < 128; ++h)
                a += __ldg(&wq_l[h * 128 + i]) * wk_l[h * 256 + t];
            write_b_split((__nv_bfloat16*)g_Cb4, t, i, 8, a);
        }
    } else if (b < POOL_BLKS + 384) {
        int j = b - (POOL_BLKS + 128);   // W2 k-index 0..255
        for (int idx = t; idx < 16384; idx += 512) {
            int h = idx >> 7, m = idx & 127;
            st[m * 132 + h] = wo_l[idx];
        }
        __syncthreads();
        if (t < 128) {
            float a = 0.f;
            for (int m = 0; m < 128; ++m)
                a += __ldg(&wv_l[m * 256 + j]) * st[m * 132 + t];
            write_b_split((__nv_bfloat16*)g_W2b4, t, j, 16, a);
        }
    } else if (b == POOL_BLKS + 384) {
        if (t < 256) {
            float a = 0.f;
            for (int h = 0; h < 128; ++h) a += bq_l[h] * wk_l[h * 256 + t];
            g_c0[t] = a;
        }
    } else {
        for (int idx = t; idx < 16384; idx += 512) {
            int h = idx >> 7, m = idx & 127;
            st[m * 132 + h] = wo_l[idx];
        }
        __syncthreads();
        if (t < 128) {
            float a = 0.f;
            for (int m = 0; m < 128; ++m) a += bv_l[m] * st[m * 132 + t];
            g_bias2[t] = a + bo_l[t];
        }
    }
}

// ---------------- kernel 1b: second-stage pool reduction (37 blocks) -----
__global__ void k1b_reduce() {
    int bb = blockIdx.x, t = threadIdx.x;
    float s0 = 0.f, s1 = 0.f, s2 = 0.f, s3 = 0.f;
    int base = bb * 8;
    s0 = g_partial[(base + 0) * 512 + t] + g_partial[(base + 4) * 512 + t];
    s1 = g_partial[(base + 1) * 512 + t] + g_partial[(base + 5) * 512 + t];
    s2 = g_partial[(base + 2) * 512 + t] + g_partial[(base + 6) * 512 + t];
    s3 = g_partial[(base + 3) * 512 + t] + g_partial[(base + 7) * 512 + t];
    g_partial2[bb * 512 + t] = (s0 + s1) + (s2 + s3);
}

// ---------------- kernel 2: pooled + global-path small matrices ----------
// Fused staging: {wk_g, wv_g} -> {k_g, v_g}; then {wo_g, wq_g} -> {M, kqg, cgs}.
__global__ void k2_small(const float* __restrict__ wk_g,
                         const float* __restrict__ wv_g,
                         const float* __restrict__ wo_g,
                         const float* __restrict__ wq_g,
                         const float* __restrict__ bk_g,
                         const float* __restrict__ bv_g,
                         const float* __restrict__ bq_g,
                         float* __restrict__ out_pooled) {
    extern __shared__ float st[];       // 2 x 16896 floats
    float* st2 = st + 16896;
    int t = threadIdx.x;

    // reduce 37 second-stage partials (8-way ILP + 5 tail)
    {
        float s0 = 0.f, s1 = 0.f, s2 = 0.f, s3 = 0.f;
        float s4 = 0.f, s5 = 0.f, s6 = 0.f, s7 = 0.f;
        #pragma unroll
        for (int b = 0; b < 32; b += 8) {
            s0 += g_partial2[(b + 0) * 512 + t];
            s1 += g_partial2[(b + 1) * 512 + t];
            s2 += g_partial2[(b + 2) * 512 + t];
            s3 += g_partial2[(b + 3) * 512 + t];
            s4 += g_partial2[(b + 4) * 512 + t];
            s5 += g_partial2[(b + 5) * 512 + t];
            s6 += g_partial2[(b + 6) * 512 + t];
            s7 += g_partial2[(b + 7) * 512 + t];
        }
        s0 += g_partial2[32 * 512 + t];
        s1 += g_partial2[33 * 512 + t];
        s2 += g_partial2[34 * 512 + t];
        s3 += g_partial2[35 * 512 + t];
        s4 += g_partial2[36 * 512 + t];
        float s = ((s0 + s1) + (s2 + s3)) + ((s4 + s5) + (s6 + s7));
        s *= (1.0f / NN);
        g_pooled[t] = s;
        out_pooled[t] = s;
    }

    // stage wk_g and wv_g together (transposed)
    for (int idx = t; idx < 16384; idx += 512) {
        int h = idx >> 7, j = idx & 127;
        st[j * 132 + h]  = wk_g[idx];
        st2[j * 132 + h] = wv_g[idx];
    }
    __syncthreads();
    {
        int si = t >> 7, h = t & 127;
        float a = 0.f, a2 = 0.f;
        for (int j = 0; j < 128; ++j) {
            float p = g_pooled[si * 128 + j];
            a  += p * st[j * 132 + h];
            a2 += p * st2[j * 132 + h];
        }
        g_kg[t] = a + bk_g[h];
        g_vg[t] = a2 + bv_g[h];
    }
    __syncthreads();

    // stage wo_g and wq_g together (transposed)
    for (int idx = t; idx < 16384; idx += 512) {
        int h = idx >> 7, m = idx & 127;
        st[m * 132 + h]  = wo_g[idx];
        st2[m * 132 + h] = wq_g[idx];
    }
    __syncthreads();
    {
        int si = t >> 7, h = t & 127;
        float a = 0.f;
        for (int m = 0; m < 128; ++m) a += g_vg[si * 128 + m] * st[m * 132 + h];
        g_M[t] = a;
    }
    {
        int i = t >> 2, si = t & 3;
        float a = 0.f;
        for (int h = 0; h < 128; ++h) a += st2[i * 132 + h] * g_kg[si * 128 + h];
        g_kqg[i * 4 + si] = a;
    }
    if (t < 4) {
        float a = 0.f;
        for (int h = 0; h < 128; ++h) a += bq_g[h] * g_kg[t * 128 + h];
        g_cgs[t] = a;
    }
}

// ---------------- kernel 3: fused per-edge kernel (256 thr, 2 CTA/SM) ----
__global__ void __launch_bounds__(256, 2)
main_edge_kernel(const float* __restrict__ ea_g,
                 const float* __restrict__ gf,
                 const int* __restrict__ ei,
                 const float* __restrict__ bo_g,
                 float* __restrict__ out,
                 float* __restrict__ attn_out) {
    extern __shared__ float smem[];
    unsigned* sEAhi = (unsigned*)smem;            // 64*68 uints
    unsigned* sEAlo = sEAhi + 64 * EA_U;          // 64*68 uints
    float*    sQK   = smem + 2 * 64 * EA_U;       // 64*260 floats
    const int tid  = threadIdx.x;
    const int wid  = tid >> 5;    // 0..7
    const int lane = tid & 31;
    const int g    = lane >> 2;   // 0..7
    const int t4   = lane & 3;    // 0..3
    const int e0   = blockIdx.x * TILE_E;

    // stage edge_attr tile pre-split to bf16 hi/lo (zero-fill OOB rows)
    for (int idx = tid; idx < 2048; idx += 256) {
        int r = idx >> 5, c = idx & 31;          // c: float4 col (k = 4c)
        float4 v = make_float4(0.f, 0.f, 0.f, 0.f);
        if (e0 + r < E_TOT) v = ((const float4*)ea_g)[(size_t)(e0 + r) * 32 + c];
        unsigned h0, l0, h1, l1;
        split_bf2(v.x, v.y, h0, l0);
        split_bf2(v.z, v.w, h1, l1);
        sEAhi[r * EA_U + 2 * c]     = h0;
        sEAhi[r * EA_U + 2 * c + 1] = h1;
        sEAlo[r * EA_U + 2 * c]     = l0;
        sEAlo[r * EA_U + 2 * c + 1] = l1;
    }
    __syncthreads();

    // ---- Phase A: qk[64][256] = ea @ C + c0 (bf16 m16n8k16, 3-term) ----
    {
        const int wm = wid >> 2;          // 0..1
        const int wn = wid & 3;           // 0..3
        const int m0 = wm * 32;
        const int n0 = wn * 64;
        float acc[2][8][4];
        #pragma unroll
        for (int am = 0; am < 2; ++am)
            #pragma unroll
            for (int bn = 0; bn < 8; ++bn)
                #pragma unroll
                for (int q = 0; q < 4; ++q) acc[am][bn][q] = 0.f;

        // ldmatrix lane base addresses (bytes): row = lane&15, half = lane>>4
        unsigned abase_hi = (unsigned)__cvta_generic_to_shared(sEAhi)
                          + (lane & 15) * (EA_U * 4) + (lane >> 4) * 16;
        unsigned abase_lo = abase_hi + 64 * EA_U * 4;

        uint4 bpc[4], bpn[4];
        #pragma unroll
        for (int b2 = 0; b2 < 4; ++b2)
            bpc[b2] = __ldg(&g_Cb4[((n0 + 8 * b2 + g) * 8 + 0) * 4 + t4]);

        #pragma unroll 1
        for (int kg = 0; kg < 8; ++kg) {
            unsigned Ah[2][4], Al[2][4];
            #pragma unroll
            for (int am = 0; am < 2; ++am) {
                unsigned roff = (m0 + 16 * am) * (EA_U * 4) + kg * 32;
                ldsm_x4(Ah[am], abase_hi + roff);
                ldsm_x4(Al[am], abase_lo + roff);
            }
            #pragma unroll
            for (int b2 = 0; b2 < 4; ++b2)
                bpn[b2] = __ldg(&g_Cb4[((n0 + 32 + 8 * b2 + g) * 8 + kg) * 4 + t4]);
            #pragma unroll
            for (int b2 = 0; b2 < 4; ++b2) {
                #pragma unroll
                for (int am = 0; am < 2; ++am) {
                    mma16(acc[am][b2], Ah[am], bpc[b2].x, bpc[b2].y);
                    mma16(acc[am][b2], Ah[am], bpc[b2].z, bpc[b2].w);
                    mma16(acc[am][b2], Al[am], bpc[b2].x, bpc[b2].y);
                }
            }
            if (kg < 7) {
                #pragma unroll
                for (int b2 = 0; b2 < 4; ++b2)
                    bpc[b2] = __ldg(&g_Cb4[((n0 + 8 * b2 + g) * 8 + kg + 1) * 4 + t4]);
            }
            #pragma unroll
            for (int b2 = 0; b2 < 4; ++b2) {
                #pragma unroll
                for (int am = 0; am < 2; ++am) {
                    mma16(acc[am][4 + b2], Ah[am], bpn[b2].x, bpn[b2].y);
                    mma16(acc[am][4 + b2], Ah[am], bpn[b2].z, bpn[b2].w);
                    mma16(acc[am][4 + b2], Al[am], bpn[b2].x, bpn[b2].y);
                }
            }
        }

        // epilogue: qk + c0 -> sQK
        #pragma unroll
        for (int am = 0; am < 2; ++am) {
            #pragma unroll
            for (int bn = 0; bn < 8; ++bn) {
                int col = n0 + 8 * bn + 2 * t4;
                float2 c0v = *(const float2*)&g_c0[col];
                int r1 = m0 + 16 * am + g;
                *(float2*)&sQK[r1 * QK_S + col] =
                    make_float2(acc[am][bn][0] + c0v.x, acc[am][bn][1] + c0v.y);
                *(float2*)&sQK[(r1 + 8) * QK_S + col] =
                    make_float2(acc[am][bn][2] + c0v.x, acc[am][bn][3] + c0v.y);
            }
        }
    }
    __syncthreads();

    // ---- Phase B: gather + local softmax + pooled feats + global path ----
    int idx0[8], idx1[8];
    #pragma unroll
    for (int r = 0; r < 8; ++r) {
        int eg = e0 + 8 * wid + r;
        int egc = eg < E_TOT ? eg : E_TOT - 1;
        idx0[r] = ei[egc];
        idx1[r] = ei[E_TOT + egc];
    }
    #pragma unroll 2
    for (int r = 0; r < 8; ++r) {
        int el = 8 * wid + r;
        int eg = e0 + el;
        if (eg < E_TOT) {
            const float4* srcp = (const float4*)(gf + (size_t)idx0[r] * 512);
            const float4* dstp = (const float4*)(gf + (size_t)idx1[r] * 512);
            float4 sv[4], dv[4];
            #pragma unroll
            for (int s2 = 0; s2 < 4; ++s2) {
                sv[s2] = srcp[s2 * 32 + lane];
                dv[s2] = dstp[s2 * 32 + lane];
            }

            // gather-independent work under the loads
            unsigned hu0 = sEAhi[el * EA_U + 2 * lane];
            unsigned hu1 = sEAhi[el * EA_U + 2 * lane + 1];
            unsigned lu0 = sEAlo[el * EA_U + 2 * lane];
            unsigned lu1 = sEAlo[el * EA_U + 2 * lane + 1];
            float2 hf0 = __bfloat1622float2(u_as_bf2(hu0));
            float2 hf1 = __bfloat1622float2(u_as_bf2(hu1));
            float2 lf0 = __bfloat1622float2(u_as_bf2(lu0));
            float2 lf1 = __bfloat1622float2(u_as_bf2(lu1));
            float4 eav = make_float4(hf0.x + lf0.x, hf0.y + lf0.y,
                                     hf1.x + lf1.x, hf1.y + lf1.y);
            float4 kq0 = ((const float4*)g_kqg)[4 * lane + 0];
            float4 kq1 = ((const float4*)g_kqg)[4 * lane + 1];
            float4 kq2 = ((const float4*)g_kqg)[4 * lane + 2];
            float4 kq3 = ((const float4*)g_kqg)[4 * lane + 3];
            float g0 = eav.x*kq0.x + eav.y*kq1.x + eav.z*kq2.x + eav.w*kq3.x;
            float g1 = eav.x*kq0.y + eav.y*kq1.y + eav.z*kq2.y + eav.w*kq3.y;
            float g2 = eav.x*kq0.z + eav.y*kq1.z + eav.z*kq2.z + eav.w*kq3.z;
            float g3 = eav.x*kq0.w + eav.y*kq1.w + eav.z*kq2.w + eav.w*kq3.w;
            float4 qlo = *(const float4*)&sQK[el * QK_S + 4 * lane];
            float4 qhi = *(const float4*)&sQK[el * QK_S + 128 + 4 * lane];

            float sc0 = dot4(qlo, sv[0]) + dot4(qhi, dv[0]);
            float sc1 = dot4(qlo, sv[1]) + dot4(qhi, dv[1]);
            float sc2 = dot4(qlo, sv[2]) + dot4(qhi, dv[2]);
            float sc3 = dot4(qlo, sv[3]) + dot4(qhi, dv[3]);

            // merged 8-value butterfly reduction
            #pragma unroll
            for (int o = 16; o > 0; o >>= 1) {
                sc0 += __shfl_xor_sync(0xFFFFFFFFu, sc0, o);
                sc1 += __shfl_xor_sync(0xFFFFFFFFu, sc1, o);
                sc2 += __shfl_xor_sync(0xFFFFFFFFu, sc2, o);
                sc3 += __shfl_xor_sync(0xFFFFFFFFu, sc3, o);
                g0  += __shfl_xor_sync(0xFFFFFFFFu, g0, o);
                g1  += __shfl_xor_sync(0xFFFFFFFFu, g1, o);
                g2  += __shfl_xor_sync(0xFFFFFFFFu, g2, o);
                g3  += __shfl_xor_sync(0xFFFFFFFFu, g3, o);
            }

            float z0 = sc0 * SCALE, z1 = sc1 * SCALE, z2 = sc2 * SCALE, z3 = sc3 * SCALE;
            float mz = fmaxf(fmaxf(z0, z1), fmaxf(z2, z3));
            float a0 = __expf(z0 - mz), a1 = __expf(z1 - mz);
            float a2 = __expf(z2 - mz), a3 = __expf(z3 - mz);
            float inv = 1.f / (a0 + a1 + a2 + a3);
            a0 *= inv; a1 *= inv; a2 *= inv; a3 *= inv;
            float4 plo, phi;
            plo.x = a0*sv[0].x + a1*sv[1].x + a2*sv[2].x + a3*sv[3].x;
            plo.y = a0*sv[0].y + a1*sv[1].y + a2*sv[2].y + a3*sv[3].y;
            plo.z = a0*sv[0].z + a1*sv[1].z + a2*sv[2].z + a3*sv[3].z;
            plo.w = a0*sv[0].w + a1*sv[1].w + a2*sv[2].w + a3*sv[3].w;
            phi.x = a0*dv[0].x + a1*dv[1].x + a2*dv[2].x + a3*dv[3].x;
            phi.y = a0*dv[0].y + a1*dv[1].y + a2*dv[2].y + a3*dv[3].y;
            phi.z = a0*dv[0].z + a1*dv[1].z + a2*dv[2].z + a3*dv[3].z;
            phi.w = a0*dv[0].w + a1*dv[1].w + a2*dv[2].w + a3*dv[3].w;
            *(float4*)&sQK[el * QK_S + 4 * lane] = plo;         // in-place pooled
            *(float4*)&sQK[el * QK_S + 128 + 4 * lane] = phi;

            float y0 = (g0 + g_cgs[0]) * SCALE, y1 = (g1 + g_cgs[1]) * SCALE;
            float y2 = (g2 + g_cgs[2]) * SCALE, y3 = (g3 + g_cgs[3]) * SCALE;
            float my = fmaxf(fmaxf(y0, y1), fmaxf(y2, y3));
            float b0 = __expf(y0 - my), b1 = __expf(y1 - my);
            float b2 = __expf(y2 - my), b3 = __expf(y3 - my);
            float binv = 1.f / (b0 + b1 + b2 + b3);
            b0 *= binv; b1 *= binv; b2 *= binv; b3 *= binv;
            if (lane == 0) {
                float* ap = attn_out + (size_t)eg * 4;
                ap[0] = b0; ap[1] = b1; ap[2] = b2; ap[3] = b3;
            }
            float4 m0v = ((const float4*)g_M)[lane];
            float4 m1v = ((const float4*)g_M)[32 + lane];
            float4 m2v = ((const float4*)g_M)[64 + lane];
            float4 m3v = ((const float4*)g_M)[96 + lane];
            float4 bo4 = ((const float4*)bo_g)[lane];
            float4 go;
            go.x = b0*m0v.x + b1*m1v.x + b2*m2v.x + b3*m3v.x + bo4.x;
            go.y = b0*m0v.y + b1*m1v.y + b2*m2v.y + b3*m3v.y + bo4.y;
            go.z = b0*m0v.z + b1*m1v.z + b2*m2v.z + b3*m3v.z + bo4.z;
            go.w = b0*m0v.w + b1*m1v.w + b2*m2v.w + b3*m3v.w + bo4.w;
            float* orow = out + (size_t)eg * 384;
            ((float4*)orow)[lane] = eav;
            ((float4*)(orow + 256))[lane] = go;
        }
    }
    __syncthreads();

    // ---- Phase C: local_out[64][128] = pooled @ W2^T + bias2 (bf16) ----
    {
        const int cm = wid >> 2;         // 0..1
        const int cn = wid & 3;          // 0..3
        const int m0 = cm * 32;
        const int n0 = cn * 32;
        float acc[2][4][4];
        #pragma unroll
        for (int am = 0; am < 2; ++am)
            #pragma unroll
            for (int bn = 0; bn < 4; ++bn)
                #pragma unroll
                for (int q = 0; q < 4; ++q) acc[am][bn][q] = 0.f;

        uint4 bp0[4], bp1[4];
        #pragma unroll
        for (int bn = 0; bn < 4; ++bn)
            bp0[bn] = __ldg(&g_W2b4[((n0 + 8 * bn + g) * 16 + 0) * 4 + t4]);

        #pragma unroll 1
        for (int kg = 0; kg < 16; kg += 2) {
            #pragma unroll
            for (int bn = 0; bn < 4; ++bn)
                bp1[bn] = __ldg(&g_W2b4[((n0 + 8 * bn + g) * 16 + kg + 1) * 4 + t4]);

            {
                unsigned Ah[2][4], Al[2][4];
                #pragma unroll
                for (int am = 0; am < 2; ++am) {
                    int R = m0 + 16 * am;
                    float2 p00 = *(const float2*)&sQK[(R + g)     * QK_S + kg * 16 + 2 * t4];
                    float2 p10 = *(const float2*)&sQK[(R + g + 8) * QK_S + kg * 16 + 2 * t4];
                    float2 p01 = *(const float2*)&sQK[(R + g)     * QK_S + kg * 16 + 2 * t4 + 8];
                    float2 p11 = *(const float2*)&sQK[(R + g + 8) * QK_S + kg * 16 + 2 * t4 + 8];
                    split_bf2(p00.x, p00.y, Ah[am][0], Al[am][0]);
                    split_bf2(p10.x, p10.y, Ah[am][1], Al[am][1]);
                    split_bf2(p01.x, p01.y, Ah[am][2], Al[am][2]);
                    split_bf2(p11.x, p11.y, Ah[am][3], Al[am][3]);
                }
                #pragma unroll
                for (int bn = 0; bn < 4; ++bn) {
                    #pragma unroll
                    for (int am = 0; am < 2; ++am) {
                        mma16(acc[am][bn], Ah[am], bp0[bn].x, bp0[bn].y);
                        mma16(acc[am][bn], Ah[am], bp0[bn].z, bp0[bn].w);
                        mma16(acc[am][bn], Al[am], bp0[bn].x, bp0[bn].y);
                    }
                }
            }

            if (kg + 2 < 16) {
                #pragma unroll
                for (int bn = 0; bn < 4; ++bn)
                    bp0[bn] = __ldg(&g_W2b4[((n0 + 8 * bn + g) * 16 + kg + 2) * 4 + t4]);
            }

            {
                unsigned Ah[2][4], Al[2][4];
                #pragma unroll
                for (int am = 0; am < 2; ++am) {
                    int R = m0 + 16 * am;
                    float2 p00 = *(const float2*)&sQK[(R + g)     * QK_S + (kg+1) * 16 + 2 * t4];
                    float2 p10 = *(const float2*)&sQK[(R + g + 8) * QK_S + (kg+1) * 16 + 2 * t4];
                    float2 p01 = *(const float2*)&sQK[(R + g)     * QK_S + (kg+1) * 16 + 2 * t4 + 8];
                    float2 p11 = *(const float2*)&sQK[(R + g + 8) * QK_S + (kg+1) * 16 + 2 * t4 + 8];
                    split_bf2(p00.x, p00.y, Ah[am][0], Al[am][0]);
                    split_bf2(p10.x, p10.y, Ah[am][1], Al[am][1]);
                    split_bf2(p01.x, p01.y, Ah[am][2], Al[am][2]);
                    split_bf2(p11.x, p11.y, Ah[am][3], Al[am][3]);
                }
                #pragma unroll
                for (int bn = 0; bn < 4; ++bn) {
                    #pragma unroll
                    for (int am = 0; am < 2; ++am) {
                        mma16(acc[am][bn], Ah[am], bp1[bn].x, bp1[bn].y);
                        mma16(acc[am][bn], Ah[am], bp1[bn].z, bp1[bn].w);
                        mma16(acc[am][bn], Al[am], bp1[bn].x, bp1[bn].y);
                    }
                }
            }
        }

        // epilogue: + bias2 -> out[:, 128:256]
        #pragma unroll
        for (int am = 0; am < 2; ++am) {
            #pragma unroll
            for (int bn = 0; bn < 4; ++bn) {
                int h = n0 + 8 * bn + 2 * t4;
                float2 bv = *(const float2*)&g_bias2[h];
                int e1 = e0 + m0 + 16 * am + g;
                if (e1 < E_TOT) {
                    *(float2*)&out[(size_t)e1 * 384 + 128 + h] =
                        make_float2(acc[am][bn][0] + bv.x, acc[am][bn][1] + bv.y);
                }
                int e2 = e1 + 8;
                if (e2 < E_TOT) {
                    *(float2*)&out[(size_t)e2 * 384 + 128 + h] =
                        make_float2(acc[am][bn][2] + bv.x, acc[am][bn][3] + bv.y);
                }
            }
        }
    }
}

// ---------------- launch ---------------------------------------------------
extern "C" void kernel_launch(void* const* d_in, const int* in_sizes, int n_in,
                              void* d_out, int out_size) {
    const float* ea   = (const float*)d_in[0];
    const float* gf   = (const float*)d_in[1];
    const int*   ei   = (const int*)d_in[2];
    const float* wq_l = (const float*)d_in[3];
    const float* wk_l = (const float*)d_in[4];
    const float* wv_l = (const float*)d_in[5];
    const float* bq_l = (const float*)d_in[6];
    const float* bv_l = (const float*)d_in[8];
    const float* wo_l = (const float*)d_in[9];
    const float* bo_l = (const float*)d_in[10];
    const float* wq_g = (const float*)d_in[11];
    const float* wk_g = (const float*)d_in[12];
    const float* wv_g = (const float*)d_in[13];
    const float* bq_g = (const float*)d_in[14];
    const float* bk_g = (const float*)d_in[15];
    const float* bv_g = (const float*)d_in[16];
    const float* wo_g = (const float*)d_in[17];
    const float* bo_g = (const float*)d_in[18];

    float* out        = (float*)d_out;
    float* out_pooled = out + (size_t)E_TOT * 384;
    float* out_attn   = out_pooled + 512;

    const int MAIN_SMEM = (2 * 64 * EA_U + 16640) * 4;   // 101376 B
    const int K2_SMEM   = 2 * 16896 * 4;                  // 135168 B

    cudaFuncSetAttribute(k1_precompute,
                         cudaFuncAttributeMaxDynamicSharedMemorySize, 67584);
    cudaFuncSetAttribute(k2_small,
                         cudaFuncAttributeMaxDynamicSharedMemorySize, K2_SMEM);
    cudaFuncSetAttribute(main_edge_kernel,
                         cudaFuncAttributeMaxDynamicSharedMemorySize, MAIN_SMEM);

    k1_precompute<<<POOL_BLKS + 386, 512, 67584>>>(gf, wq_l, wk_l, wv_l, wo_l,
                                                   bq_l, bv_l, bo_l);
    k1b_reduce<<<POOL2_BLKS, 512>>>();
    k2_small<<<1, 512, K2_SMEM>>>(wk_g, wv_g, wo_g, wq_g,
                                  bk_g, bv_g, bq_g, out_pooled);
    main_edge_kernel<<<GRID_MAIN, 256, MAIN_SMEM>>>(ea, gf, ei, bo_g, out, out_attn);
}

// round 16
// speedup vs baseline: 1.0616x; 1.0208x over previous
#include <cuda_runtime.h>
#include <cuda_bf16.h>

#define E_TOT   100000
#define NN      50000
#define POOL_BLKS 296
#define ROWS_PER_BLK 169
#define POOL2_BLKS 37          /* 296 / 8 */
#define TILE_E  64
#define GRID_MAIN ((E_TOT + TILE_E - 1) / TILE_E)
#define EA_U    68      /* sEAhi/sEAlo row stride in uints (64 data + 4 pad) */
#define QK_S    260     /* sQK row stride (floats) */
#define SCALE   0.08838834764831845f   /* 1/sqrt(128) */

// ---------------- device scratch ----------------
__device__ float g_partial[POOL_BLKS * 512];
__device__ float g_partial2[POOL2_BLKS * 512];
__device__ float g_pooled[512];
__device__ float g_kg[512];
__device__ float g_vg[512];
__device__ float g_M[512];          // [4][128] = v_g @ wo_g^T
__device__ float g_kqg[512];        // [128][4]
__device__ float g_cgs[4];
__device__ float g_c0[256];         // bq_l @ wk_l
__device__ float g_bias2[128];      // bv_l @ wo_l^T + bo_l
// B matrices pre-split to bf16 hi/lo in m16n8k16 fragment order:
__device__ uint4 g_Cb4[256 * 8 * 4];    // C:  n=256, k=128 (kg 0..7)
__device__ uint4 g_W2b4[128 * 16 * 4];  // W2: n=128, k=256 (kg 0..15)

__device__ __forceinline__ float dot4(float4 a, float4 b) {
    return a.x * b.x + a.y * b.y + a.z * b.z + a.w * b.w;
}

__device__ __forceinline__ void mma16(float* d, const unsigned* a, unsigned b0, unsigned b1) {
    asm volatile(
        "mma.sync.aligned.m16n8k16.row.col.f32.bf16.bf16.f32 "
        "{%0,%1,%2,%3}, {%4,%5,%6,%7}, {%8,%9}, {%0,%1,%2,%3};"
        : "+f"(d[0]), "+f"(d[1]), "+f"(d[2]), "+f"(d[3])
        : "r"(a[0]), "r"(a[1]), "r"(a[2]), "r"(a[3]), "r"(b0), "r"(b1));
}

__device__ __forceinline__ unsigned bf2_as_u(__nv_bfloat162 h) {
    return *(unsigned*)&h;
}
__device__ __forceinline__ __nv_bfloat162 u_as_bf2(unsigned u) {
    return *(__nv_bfloat162*)&u;
}

// split float pair -> hi bf16x2, lo bf16x2
__device__ __forceinline__ void split_bf2(float x, float y, unsigned& hi, unsigned& lo) {
    __nv_bfloat162 h = __float22bfloat162_rn(make_float2(x, y));
    float2 hf = __bfloat1622float2(h);
    __nv_bfloat162 l = __float22bfloat162_rn(make_float2(x - hf.x, y - hf.y));
    hi = bf2_as_u(h);
    lo = bf2_as_u(l);
}

// write one fp32 value as pre-split bf16 hi/lo into fragment-ordered array.
__device__ __forceinline__ void write_b_split(__nv_bfloat16* base, int n, int k,
                                              int kgs, float v) {
    int kg = k >> 4, r = k & 15;
    int word, t4;
    if (r < 8) { t4 = r >> 1; word = 0; }
    else       { t4 = (r - 8) >> 1; word = 1; }
    int half = r & 1;
    size_t bidx = ((((size_t)(n * kgs + kg) * 4 + t4) * 4 + word) * 2 + half);
    __nv_bfloat16 hi = __float2bfloat16(v);
    __nv_bfloat16 lo = __float2bfloat16(v - __bfloat162float(hi));
    base[bidx] = hi;
    base[bidx + 4] = lo;
}

// ---------------- kernel 1: pool partials + C + W2 + c0 + bias2 ----------
// blocks 0..295: pool partial (float4, 4 rows in flight);
// 296..423: C k-rows; 424..679: W2 k-cols; 680: c0; 681: bias2.
__global__ void k1_precompute(const float* __restrict__ gf,
                              const float* __restrict__ wq_l,
                              const float* __restrict__ wk_l,
                              const float* __restrict__ wv_l,
                              const float* __restrict__ wo_l,
                              const float* __restrict__ bq_l,
                              const float* __restrict__ bv_l,
                              const float* __restrict__ bo_l) {
    extern __shared__ float st[];
    int b = blockIdx.x, t = threadIdx.x;
    if (b < POOL_BLKS) {
        int r0 = b * ROWS_PER_BLK;
        int nrows = NN - r0;
        if (nrows > ROWS_PER_BLK) nrows = ROWS_PER_BLK;
        int tq = t & 127;          // float4 column group
        int tr = t >> 7;           // row offset 0..3
        const float4* p4 = (const float4*)gf;
        float4 a0 = make_float4(0.f, 0.f, 0.f, 0.f);
        float4 a1 = a0, a2 = a0, a3 = a0;
        for (int r = 0; r < nrows; r += 16) {
            int rr0 = r + tr;
            int rr1 = r + 4 + tr;
            int rr2 = r + 8 + tr;
            int rr3 = r + 12 + tr;
            if (rr0 < nrows) {
                float4 v = p4[(size_t)(r0 + rr0) * 128 + tq];
                a0.x += v.x; a0.y += v.y; a0.z += v.z; a0.w += v.w;
            }
            if (rr1 < nrows) {
                float4 v = p4[(size_t)(r0 + rr1) * 128 + tq];
                a1.x += v.x; a1.y += v.y; a1.z += v.z; a1.w += v.w;
            }
            if (rr2 < nrows) {
                float4 v = p4[(size_t)(r0 + rr2) * 128 + tq];
                a2.x += v.x; a2.y += v.y; a2.z += v.z; a2.w += v.w;
            }
            if (rr3 < nrows) {
                float4 v = p4[(size_t)(r0 + rr3) * 128 + tq];
                a3.x += v.x; a3.y += v.y; a3.z += v.z; a3.w += v.w;
            }
        }
        float4 acc = make_float4((a0.x + a1.x) + (a2.x + a3.x),
                                 (a0.y + a1.y) + (a2.y + a3.y),
                                 (a0.z + a1.z) + (a2.z + a3.z),
                                 (a0.w + a1.w) + (a2.w + a3.w));
        float4* st4 = (float4*)st;
        st4[tr * 128 + tq] = acc;
        __syncthreads();
        if (t < 128) {
            float4 s0 = st4[t], s1 = st4[128 + t], s2 = st4[256 + t], s3 = st4[384 + t];
            float4 s = make_float4((s0.x + s1.x) + (s2.x + s3.x),
                                   (s0.y + s1.y) + (s2.y + s3.y),
                                   (s0.z + s1.z) + (s2.z + s3.z),
                                   (s0.w + s1.w) + (s2.w + s3.w));
            ((float4*)g_partial)[b * 128 + t] = s;
        }
    } else if (b < POOL_BLKS + 128) {
        int i = b - POOL_BLKS;      // C k-row 0..127
        if (t < 256) {
            float a = 0.f;
            for (int h = 0; h < 128; ++h)
                a += __ldg(&wq_l[h * 128 + i]) * wk_l[h * 256 + t];
            write_b_split((__nv_bfloat16*)g_Cb4, t, i, 8, a);
        }
    } else if (b < POOL_BLKS + 384) {
        int j = b - (POOL_BLKS + 128);   // W2 k-index 0..255
        for (int idx = t; idx < 16384; idx += 512) {
            int h = idx >> 7, m = idx & 127;
            st[m * 132 + h] = wo_l[idx];
        }
        __syncthreads();
        if (t < 128) {
            float a = 0.f;
            for (int m = 0; m < 128; ++m)
                a += __ldg(&wv_l[m * 256 + j]) * st[m * 132 + t];
            write_b_split((__nv_bfloat16*)g_W2b4, t, j, 16, a);
        }
    } else if (b == POOL_BLKS + 384) {
        if (t < 256) {
            float a = 0.f;
            for (int h = 0; h < 128; ++h) a += bq_l[h] * wk_l[h * 256 + t];
            g_c0[t] = a;
        }
    } else {
        for (int idx = t; idx < 16384; idx += 512) {
            int h = idx >> 7, m = idx & 127;
            st[m * 132 + h] = wo_l[idx];
        }
        __syncthreads();
        if (t < 128) {
            float a = 0.f;
            for (int m = 0; m < 128; ++m) a += bv_l[m] * st[m * 132 + t];
            g_bias2[t] = a + bo_l[t];
        }
    }
}

// ---------------- kernel 1b: second-stage pool reduction (37 blocks) -----
__global__ void k1b_reduce() {
    int bb = blockIdx.x, t = threadIdx.x;
    float s0, s1, s2, s3;
    int base = bb * 8;
    s0 = g_partial[(base + 0) * 512 + t] + g_partial[(base + 4) * 512 + t];
    s1 = g_partial[(base + 1) * 512 + t] + g_partial[(base + 5) * 512 + t];
    s2 = g_partial[(base + 2) * 512 + t] + g_partial[(base + 6) * 512 + t];
    s3 = g_partial[(base + 3) * 512 + t] + g_partial[(base + 7) * 512 + t];
    g_partial2[bb * 512 + t] = (s0 + s1) + (s2 + s3);
}

// ---------------- kernel 2: pooled + global-path small matrices ----------
// Fused staging: {wk_g, wv_g} -> {k_g, v_g}; then {wo_g, wq_g} -> {M, kqg, cgs}.
__global__ void k2_small(const float* __restrict__ wk_g,
                         const float* __restrict__ wv_g,
                         const float* __restrict__ wo_g,
                         const float* __restrict__ wq_g,
                         const float* __restrict__ bk_g,
                         const float* __restrict__ bv_g,
                         const float* __restrict__ bq_g,
                         float* __restrict__ out_pooled) {
    extern __shared__ float st[];       // 2 x 16896 floats
    float* st2 = st + 16896;
    int t = threadIdx.x;

    // reduce 37 second-stage partials (8-way ILP + 5 tail)
    {
        float s0 = 0.f, s1 = 0.f, s2 = 0.f, s3 = 0.f;
        float s4 = 0.f, s5 = 0.f, s6 = 0.f, s7 = 0.f;
        #pragma unroll
        for (int b = 0; b < 32; b += 8) {
            s0 += g_partial2[(b + 0) * 512 + t];
            s1 += g_partial2[(b + 1) * 512 + t];
            s2 += g_partial2[(b + 2) * 512 + t];
            s3 += g_partial2[(b + 3) * 512 + t];
            s4 += g_partial2[(b + 4) * 512 + t];
            s5 += g_partial2[(b + 5) * 512 + t];
            s6 += g_partial2[(b + 6) * 512 + t];
            s7 += g_partial2[(b + 7) * 512 + t];
        }
        s0 += g_partial2[32 * 512 + t];
        s1 += g_partial2[33 * 512 + t];
        s2 += g_partial2[34 * 512 + t];
        s3 += g_partial2[35 * 512 + t];
        s4 += g_partial2[36 * 512 + t];
        float s = ((s0 + s1) + (s2 + s3)) + ((s4 + s5) + (s6 + s7));
        s *= (1.0f / NN);
        g_pooled[t] = s;
        out_pooled[t] = s;
    }

    // stage wk_g and wv_g together (transposed)
    for (int idx = t; idx < 16384; idx += 512) {
        int h = idx >> 7, j = idx & 127;
        st[j * 132 + h]  = wk_g[idx];
        st2[j * 132 + h] = wv_g[idx];
    }
    __syncthreads();
    {
        int si = t >> 7, h = t & 127;
        float a = 0.f, a2 = 0.f;
        for (int j = 0; j < 128; ++j) {
            float p = g_pooled[si * 128 + j];
            a  += p * st[j * 132 + h];
            a2 += p * st2[j * 132 + h];
        }
        g_kg[t] = a + bk_g[h];
        g_vg[t] = a2 + bv_g[h];
    }
    __syncthreads();

    // stage wo_g and wq_g together (transposed)
    for (int idx = t; idx < 16384; idx += 512) {
        int h = idx >> 7, m = idx & 127;
        st[m * 132 + h]  = wo_g[idx];
        st2[m * 132 + h] = wq_g[idx];
    }
    __syncthreads();
    {
        int si = t >> 7, h = t & 127;
        float a = 0.f;
        for (int m = 0; m < 128; ++m) a += g_vg[si * 128 + m] * st[m * 132 + h];
        g_M[t] = a;
    }
    {
        int i = t >> 2, si = t & 3;
        float a = 0.f;
        for (int h = 0; h < 128; ++h) a += st2[i * 132 + h] * g_kg[si * 128 + h];
        g_kqg[i * 4 + si] = a;
    }
    if (t < 4) {
        float a = 0.f;
        for (int h = 0; h < 128; ++h) a += bq_g[h] * g_kg[t * 128 + h];
        g_cgs[t] = a;
    }
}

// ---------------- kernel 3: fused per-edge kernel (256 thr, 2 CTA/SM) ----
// (R9 main kernel verbatim — measured 239.1 us)
__global__ void __launch_bounds__(256, 2)
main_edge_kernel(const float* __restrict__ ea_g,
                 const float* __restrict__ gf,
                 const int* __restrict__ ei,
                 const float* __restrict__ bo_g,
                 float* __restrict__ out,
                 float* __restrict__ attn_out) {
    extern __shared__ float smem[];
    unsigned* sEAhi = (unsigned*)smem;            // 64*68 uints
    unsigned* sEAlo = sEAhi + 64 * EA_U;          // 64*68 uints
    float*    sQK   = smem + 2 * 64 * EA_U;       // 64*260 floats
    const int tid  = threadIdx.x;
    const int wid  = tid >> 5;    // 0..7
    const int lane = tid & 31;
    const int g    = lane >> 2;   // 0..7
    const int t4   = lane & 3;    // 0..3
    const int e0   = blockIdx.x * TILE_E;

    // stage edge_attr tile pre-split to bf16 hi/lo (zero-fill OOB rows)
    for (int idx = tid; idx < 2048; idx += 256) {
        int r = idx >> 5, c = idx & 31;          // c: float4 col (k = 4c)
        float4 v = make_float4(0.f, 0.f, 0.f, 0.f);
        if (e0 + r < E_TOT) v = ((const float4*)ea_g)[(size_t)(e0 + r) * 32 + c];
        unsigned h0, l0, h1, l1;
        split_bf2(v.x, v.y, h0, l0);
        split_bf2(v.z, v.w, h1, l1);
        sEAhi[r * EA_U + 2 * c]     = h0;
        sEAhi[r * EA_U + 2 * c + 1] = h1;
        sEAlo[r * EA_U + 2 * c]     = l0;
        sEAlo[r * EA_U + 2 * c + 1] = l1;
    }
    __syncthreads();

    // ---- Phase A: qk[64][256] = ea @ C + c0 (bf16 m16n8k16, 3-term) ----
    {
        const int wm = wid >> 2;          // 0..1
        const int wn = wid & 3;           // 0..3
        const int m0 = wm * 32;
        const int n0 = wn * 64;
        float acc[2][8][4];
        #pragma unroll
        for (int am = 0; am < 2; ++am)
            #pragma unroll
            for (int bn = 0; bn < 8; ++bn)
                #pragma unroll
                for (int q = 0; q < 4; ++q) acc[am][bn][q] = 0.f;

        uint4 bpc[4], bpn[4];
        #pragma unroll
        for (int b2 = 0; b2 < 4; ++b2)
            bpc[b2] = __ldg(&g_Cb4[((n0 + 8 * b2 + g) * 8 + 0) * 4 + t4]);

        #pragma unroll 1
        for (int kg = 0; kg < 8; ++kg) {
            unsigned Ah[2][4], Al[2][4];
            #pragma unroll
            for (int am = 0; am < 2; ++am) {
                int R = m0 + 16 * am;
                Ah[am][0] = sEAhi[(R + g)     * EA_U + kg * 8 + t4];
                Ah[am][1] = sEAhi[(R + g + 8) * EA_U + kg * 8 + t4];
                Ah[am][2] = sEAhi[(R + g)     * EA_U + kg * 8 + 4 + t4];
                Ah[am][3] = sEAhi[(R + g + 8) * EA_U + kg * 8 + 4 + t4];
                Al[am][0] = sEAlo[(R + g)     * EA_U + kg * 8 + t4];
                Al[am][1] = sEAlo[(R + g + 8) * EA_U + kg * 8 + t4];
                Al[am][2] = sEAlo[(R + g)     * EA_U + kg * 8 + 4 + t4];
                Al[am][3] = sEAlo[(R + g + 8) * EA_U + kg * 8 + 4 + t4];
            }
            #pragma unroll
            for (int b2 = 0; b2 < 4; ++b2)
                bpn[b2] = __ldg(&g_Cb4[((n0 + 32 + 8 * b2 + g) * 8 + kg) * 4 + t4]);
            #pragma unroll
            for (int b2 = 0; b2 < 4; ++b2) {
                #pragma unroll
                for (int am = 0; am < 2; ++am) {
                    mma16(acc[am][b2], Ah[am], bpc[b2].x, bpc[b2].y);
                    mma16(acc[am][b2], Ah[am], bpc[b2].z, bpc[b2].w);
                    mma16(acc[am][b2], Al[am], bpc[b2].x, bpc[b2].y);
                }
            }
            if (kg < 7) {
                #pragma unroll
                for (int b2 = 0; b2 < 4; ++b2)
                    bpc[b2] = __ldg(&g_Cb4[((n0 + 8 * b2 + g) * 8 + kg + 1) * 4 + t4]);
            }
            #pragma unroll
            for (int b2 = 0; b2 < 4; ++b2) {
                #pragma unroll
                for (int am = 0; am < 2; ++am) {
                    mma16(acc[am][4 + b2], Ah[am], bpn[b2].x, bpn[b2].y);
                    mma16(acc[am][4 + b2], Ah[am], bpn[b2].z, bpn[b2].w);
                    mma16(acc[am][4 + b2], Al[am], bpn[b2].x, bpn[b2].y);
                }
            }
        }

        // epilogue: qk + c0 -> sQK
        #pragma unroll
        for (int am = 0; am < 2; ++am) {
            #pragma unroll
            for (int bn = 0; bn < 8; ++bn) {
                int col = n0 + 8 * bn + 2 * t4;
                float2 c0v = *(const float2*)&g_c0[col];
                int r1 = m0 + 16 * am + g;
                *(float2*)&sQK[r1 * QK_S + col] =
                    make_float2(acc[am][bn][0] + c0v.x, acc[am][bn][1] + c0v.y);
                *(float2*)&sQK[(r1 + 8) * QK_S + col] =
                    make_float2(acc[am][bn][2] + c0v.x, acc[am][bn][3] + c0v.y);
            }
        }
    }
    __syncthreads();

    // ---- Phase B: gather + local softmax + pooled feats + global path ----
    int idx0[8], idx1[8];
    #pragma unroll
    for (int r = 0; r < 8; ++r) {
        int eg = e0 + 8 * wid + r;
        int egc = eg < E_TOT ? eg : E_TOT - 1;
        idx0[r] = ei[egc];
        idx1[r] = ei[E_TOT + egc];
    }
    #pragma unroll 2
    for (int r = 0; r < 8; ++r) {
        int el = 8 * wid + r;
        int eg = e0 + el;
        if (eg < E_TOT) {
            const float4* srcp = (const float4*)(gf + (size_t)idx0[r] * 512);
            const float4* dstp = (const float4*)(gf + (size_t)idx1[r] * 512);
            float4 sv[4], dv[4];
            #pragma unroll
            for (int s2 = 0; s2 < 4; ++s2) {
                sv[s2] = srcp[s2 * 32 + lane];
                dv[s2] = dstp[s2 * 32 + lane];
            }

            // gather-independent work under the loads
            unsigned hu0 = sEAhi[el * EA_U + 2 * lane];
            unsigned hu1 = sEAhi[el * EA_U + 2 * lane + 1];
            unsigned lu0 = sEAlo[el * EA_U + 2 * lane];
            unsigned lu1 = sEAlo[el * EA_U + 2 * lane + 1];
            float2 hf0 = __bfloat1622float2(u_as_bf2(hu0));
            float2 hf1 = __bfloat1622float2(u_as_bf2(hu1));
            float2 lf0 = __bfloat1622float2(u_as_bf2(lu0));
            float2 lf1 = __bfloat1622float2(u_as_bf2(lu1));
            float4 eav = make_float4(hf0.x + lf0.x, hf0.y + lf0.y,
                                     hf1.x + lf1.x, hf1.y + lf1.y);
            float4 kq0 = ((const float4*)g_kqg)[4 * lane + 0];
            float4 kq1 = ((const float4*)g_kqg)[4 * lane + 1];
            float4 kq2 = ((const float4*)g_kqg)[4 * lane + 2];
            float4 kq3 = ((const float4*)g_kqg)[4 * lane + 3];
            float g0 = eav.x*kq0.x + eav.y*kq1.x + eav.z*kq2.x + eav.w*kq3.x;
            float g1 = eav.x*kq0.y + eav.y*kq1.y + eav.z*kq2.y + eav.w*kq3.y;
            float g2 = eav.x*kq0.z + eav.y*kq1.z + eav.z*kq2.z + eav.w*kq3.z;
            float g3 = eav.x*kq0.w + eav.y*kq1.w + eav.z*kq2.w + eav.w*kq3.w;
            float4 qlo = *(const float4*)&sQK[el * QK_S + 4 * lane];
            float4 qhi = *(const float4*)&sQK[el * QK_S + 128 + 4 * lane];

            float sc0 = dot4(qlo, sv[0]) + dot4(qhi, dv[0]);
            float sc1 = dot4(qlo, sv[1]) + dot4(qhi, dv[1]);
            float sc2 = dot4(qlo, sv[2]) + dot4(qhi, dv[2]);
            float sc3 = dot4(qlo, sv[3]) + dot4(qhi, dv[3]);

            // merged 8-value butterfly reduction
            #pragma unroll
            for (int o = 16; o > 0; o >>= 1) {
                sc0 += __shfl_xor_sync(0xFFFFFFFFu, sc0, o);
                sc1 += __shfl_xor_sync(0xFFFFFFFFu, sc1, o);
                sc2 += __shfl_xor_sync(0xFFFFFFFFu, sc2, o);
                sc3 += __shfl_xor_sync(0xFFFFFFFFu, sc3, o);
                g0  += __shfl_xor_sync(0xFFFFFFFFu, g0, o);
                g1  += __shfl_xor_sync(0xFFFFFFFFu, g1, o);
                g2  += __shfl_xor_sync(0xFFFFFFFFu, g2, o);
                g3  += __shfl_xor_sync(0xFFFFFFFFu, g3, o);
            }

            float z0 = sc0 * SCALE, z1 = sc1 * SCALE, z2 = sc2 * SCALE, z3 = sc3 * SCALE;
            float mz = fmaxf(fmaxf(z0, z1), fmaxf(z2, z3));
            float a0 = __expf(z0 - mz), a1 = __expf(z1 - mz);
            float a2 = __expf(z2 - mz), a3 = __expf(z3 - mz);
            float inv = 1.f / (a0 + a1 + a2 + a3);
            a0 *= inv; a1 *= inv; a2 *= inv; a3 *= inv;
            float4 plo, phi;
            plo.x = a0*sv[0].x + a1*sv[1].x + a2*sv[2].x + a3*sv[3].x;
            plo.y = a0*sv[0].y + a1*sv[1].y + a2*sv[2].y + a3*sv[3].y;
            plo.z = a0*sv[0].z + a1*sv[1].z + a2*sv[2].z + a3*sv[3].z;
            plo.w = a0*sv[0].w + a1*sv[1].w + a2*sv[2].w + a3*sv[3].w;
            phi.x = a0*dv[0].x + a1*dv[1].x + a2*dv[2].x + a3*dv[3].x;
            phi.y = a0*dv[0].y + a1*dv[1].y + a2*dv[2].y + a3*dv[3].y;
            phi.z = a0*dv[0].z + a1*dv[1].z + a2*dv[2].z + a3*dv[3].z;
            phi.w = a0*dv[0].w + a1*dv[1].w + a2*dv[2].w + a3*dv[3].w;
            *(float4*)&sQK[el * QK_S + 4 * lane] = plo;         // in-place pooled
            *(float4*)&sQK[el * QK_S + 128 + 4 * lane] = phi;

            float y0 = (g0 + g_cgs[0]) * SCALE, y1 = (g1 + g_cgs[1]) * SCALE;
            float y2 = (g2 + g_cgs[2]) * SCALE, y3 = (g3 + g_cgs[3]) * SCALE;
            float my = fmaxf(fmaxf(y0, y1), fmaxf(y2, y3));
            float b0 = __expf(y0 - my), b1 = __expf(y1 - my);
            float b2 = __expf(y2 - my), b3 = __expf(y3 - my);
            float binv = 1.f / (b0 + b1 + b2 + b3);
            b0 *= binv; b1 *= binv; b2 *= binv; b3 *= binv;
            if (lane == 0) {
                float* ap = attn_out + (size_t)eg * 4;
                ap[0] = b0; ap[1] = b1; ap[2] = b2; ap[3] = b3;
            }
            float4 m0v = ((const float4*)g_M)[lane];
            float4 m1v = ((const float4*)g_M)[32 + lane];
            float4 m2v = ((const float4*)g_M)[64 + lane];
            float4 m3v = ((const float4*)g_M)[96 + lane];
            float4 bo4 = ((const float4*)bo_g)[lane];
            float4 go;
            go.x = b0*m0v.x + b1*m1v.x + b2*m2v.x + b3*m3v.x + bo4.x;
            go.y = b0*m0v.y + b1*m1v.y + b2*m2v.y + b3*m3v.y + bo4.y;
            go.z = b0*m0v.z + b1*m1v.z + b2*m2v.z + b3*m3v.z + bo4.z;
            go.w = b0*m0v.w + b1*m1v.w + b2*m2v.w + b3*m3v.w + bo4.w;
            float* orow = out + (size_t)eg * 384;
            ((float4*)orow)[lane] = eav;
            ((float4*)(orow + 256))[lane] = go;
        }
    }
    __syncthreads();

    // ---- Phase C: local_out[64][128] = pooled @ W2^T + bias2 (bf16) ----
    {
        const int cm = wid >> 2;         // 0..1
        const int cn = wid & 3;          // 0..3
        const int m0 = cm * 32;
        const int n0 = cn * 32;
        float acc[2][4][4];
        #pragma unroll
        for (int am = 0; am < 2; ++am)
            #pragma unroll
            for (int bn = 0; bn < 4; ++bn)
                #pragma unroll
                for (int q = 0; q < 4; ++q) acc[am][bn][q] = 0.f;

        uint4 bp0[4], bp1[4];
        #pragma unroll
        for (int bn = 0; bn < 4; ++bn)
            bp0[bn] = __ldg(&g_W2b4[((n0 + 8 * bn + g) * 16 + 0) * 4 + t4]);

        #pragma unroll 1
        for (int kg = 0; kg < 16; kg += 2) {
            #pragma unroll
            for (int bn = 0; bn < 4; ++bn)
                bp1[bn] = __ldg(&g_W2b4[((n0 + 8 * bn + g) * 16 + kg + 1) * 4 + t4]);

            {
                unsigned Ah[2][4], Al[2][4];
                #pragma unroll
                for (int am = 0; am < 2; ++am) {
                    int R = m0 + 16 * am;
                    float2 p00 = *(const float2*)&sQK[(R + g)     * QK_S + kg * 16 + 2 * t4];
                    float2 p10 = *(const float2*)&sQK[(R + g + 8) * QK_S + kg * 16 + 2 * t4];
                    float2 p01 = *(const float2*)&sQK[(R + g)     * QK_S + kg * 16 + 2 * t4 + 8];
                    float2 p11 = *(const float2*)&sQK[(R + g + 8) * QK_S + kg * 16 + 2 * t4 + 8];
                    split_bf2(p00.x, p00.y, Ah[am][0], Al[am][0]);
                    split_bf2(p10.x, p10.y, Ah[am][1], Al[am][1]);
                    split_bf2(p01.x, p01.y, Ah[am][2], Al[am][2]);
                    split_bf2(p11.x, p11.y, Ah[am][3], Al[am][3]);
                }
                #pragma unroll
                for (int bn = 0; bn < 4; ++bn) {
                    #pragma unroll
                    for (int am = 0; am < 2; ++am) {
                        mma16(acc[am][bn], Ah[am], bp0[bn].x, bp0[bn].y);
                        mma16(acc[am][bn], Ah[am], bp0[bn].z, bp0[bn].w);
                        mma16(acc[am][bn], Al[am], bp0[bn].x, bp0[bn].y);
                    }
                }
            }

            if (kg + 2 < 16) {
                #pragma unroll
                for (int bn = 0; bn < 4; ++bn)
                    bp0[bn] = __ldg(&g_W2b4[((n0 + 8 * bn + g) * 16 + kg + 2) * 4 + t4]);
            }

            {
                unsigned Ah[2][4], Al[2][4];
                #pragma unroll
                for (int am = 0; am < 2; ++am) {
                    int R = m0 + 16 * am;
                    float2 p00 = *(const float2*)&sQK[(R + g)     * QK_S + (kg+1) * 16 + 2 * t4];
                    float2 p10 = *(const float2*)&sQK[(R + g + 8) * QK_S + (kg+1) * 16 + 2 * t4];
                    float2 p01 = *(const float2*)&sQK[(R + g)     * QK_S + (kg+1) * 16 + 2 * t4 + 8];
                    float2 p11 = *(const float2*)&sQK[(R + g + 8) * QK_S + (kg+1) * 16 + 2 * t4 + 8];
                    split_bf2(p00.x, p00.y, Ah[am][0], Al[am][0]);
                    split_bf2(p10.x, p10.y, Ah[am][1], Al[am][1]);
                    split_bf2(p01.x, p01.y, Ah[am][2], Al[am][2]);
                    split_bf2(p11.x, p11.y, Ah[am][3], Al[am][3]);
                }
                #pragma unroll
                for (int bn = 0; bn < 4; ++bn) {
                    #pragma unroll
                    for (int am = 0; am < 2; ++am) {
                        mma16(acc[am][bn], Ah[am], bp1[bn].x, bp1[bn].y);
                        mma16(acc[am][bn], Ah[am], bp1[bn].z, bp1[bn].w);
                        mma16(acc[am][bn], Al[am], bp1[bn].x, bp1[bn].y);
                    }
                }
            }
        }

        // epilogue: + bias2 -> out[:, 128:256]
        #pragma unroll
        for (int am = 0; am < 2; ++am) {
            #pragma unroll
            for (int bn = 0; bn < 4; ++bn) {
                int h = n0 + 8 * bn + 2 * t4;
                float2 bv = *(const float2*)&g_bias2[h];
                int e1 = e0 + m0 + 16 * am + g;
                if (e1 < E_TOT) {
                    *(float2*)&out[(size_t)e1 * 384 + 128 + h] =
                        make_float2(acc[am][bn][0] + bv.x, acc[am][bn][1] + bv.y);
                }
                int e2 = e1 + 8;
                if (e2 < E_TOT) {
                    *(float2*)&out[(size_t)e2 * 384 + 128 + h] =
                        make_float2(acc[am][bn][2] + bv.x, acc[am][bn][3] + bv.y);
                }
            }
        }
    }
}

// ---------------- launch ---------------------------------------------------
extern "C" void kernel_launch(void* const* d_in, const int* in_sizes, int n_in,
                              void* d_out, int out_size) {
    const float* ea   = (const float*)d_in[0];
    const float* gf   = (const float*)d_in[1];
    const int*   ei   = (const int*)d_in[2];
    const float* wq_l = (const float*)d_in[3];
    const float* wk_l = (const float*)d_in[4];
    const float* wv_l = (const float*)d_in[5];
    const float* bq_l = (const float*)d_in[6];
    const float* bv_l = (const float*)d_in[8];
    const float* wo_l = (const float*)d_in[9];
    const float* bo_l = (const float*)d_in[10];
    const float* wq_g = (const float*)d_in[11];
    const float* wk_g = (const float*)d_in[12];
    const float* wv_g = (const float*)d_in[13];
    const float* bq_g = (const float*)d_in[14];
    const float* bk_g = (const float*)d_in[15];
    const float* bv_g = (const float*)d_in[16];
    const float* wo_g = (const float*)d_in[17];
    const float* bo_g = (const float*)d_in[18];

    float* out        = (float*)d_out;
    float* out_pooled = out + (size_t)E_TOT * 384;
    float* out_attn   = out_pooled + 512;

    const int MAIN_SMEM = (2 * 64 * EA_U + 16640) * 4;   // 101376 B
    const int K2_SMEM   = 2 * 16896 * 4;                  // 135168 B

    cudaFuncSetAttribute(k1_precompute,
                         cudaFuncAttributeMaxDynamicSharedMemorySize, 67584);
    cudaFuncSetAttribute(k2_small,
                         cudaFuncAttributeMaxDynamicSharedMemorySize, K2_SMEM);
    cudaFuncSetAttribute(main_edge_kernel,
                         cudaFuncAttributeMaxDynamicSharedMemorySize, MAIN_SMEM);

    k1_precompute<<<POOL_BLKS + 386, 512, 67584>>>(gf, wq_l, wk_l, wv_l, wo_l,
                                                   bq_l, bv_l, bo_l);
    k1b_reduce<<<POOL2_BLKS, 512>>>();
    k2_small<<<1, 512, K2_SMEM>>>(wk_g, wv_g, wo_g, wq_g,
                                  bk_g, bv_g, bq_g, out_pooled);
    main_edge_kernel<<<GRID_MAIN, 256, MAIN_SMEM>>>(ea, gf, ei, bo_g, out, out_attn);
}

// round 17
// speedup vs baseline: 1.0944x; 1.0309x over previous
#include <cuda_runtime.h>
#include <cuda_bf16.h>

#define E_TOT   100000
#define NN      50000
#define POOL_BLKS 296
#define ROWS_PER_BLK 169
#define POOL2_BLKS 37          /* 296 / 8 */
#define TILE_E  64
#define GRID_MAIN ((E_TOT + TILE_E - 1) / TILE_E)
#define EA_U    68      /* sEAhi/sEAlo row stride in uints (64 data + 4 pad) */
#define QK_S    260     /* sQK row stride (floats) */
#define SCALE   0.08838834764831845f   /* 1/sqrt(128) */

// ---------------- device scratch ----------------
__device__ float g_partial[POOL_BLKS * 512];
__device__ float g_partial2[POOL2_BLKS * 512];
__device__ float g_pooled[512];
__device__ float g_kg[512];
__device__ float g_vg[512];
__device__ float g_M[512];          // [4][128] = v_g @ wo_g^T
__device__ float g_kqg[512];        // [128][4]
__device__ float g_cgs[4];
__device__ float g_c0[256];         // bq_l @ wk_l
__device__ float g_bias2[128];      // bv_l @ wo_l^T + bo_l
// B matrices pre-split to bf16 hi/lo in m16n8k16 fragment order:
__device__ uint4 g_Cb4[256 * 8 * 4];    // C:  n=256, k=128 (kg 0..7)
__device__ uint4 g_W2b4[128 * 16 * 4];  // W2: n=128, k=256 (kg 0..15)

__device__ __forceinline__ float dot4(float4 a, float4 b) {
    return a.x * b.x + a.y * b.y + a.z * b.z + a.w * b.w;
}

__device__ __forceinline__ void mma16(float* d, const unsigned* a, unsigned b0, unsigned b1) {
    asm volatile(
        "mma.sync.aligned.m16n8k16.row.col.f32.bf16.bf16.f32 "
        "{%0,%1,%2,%3}, {%4,%5,%6,%7}, {%8,%9}, {%0,%1,%2,%3};"
        : "+f"(d[0]), "+f"(d[1]), "+f"(d[2]), "+f"(d[3])
        : "r"(a[0]), "r"(a[1]), "r"(a[2]), "r"(a[3]), "r"(b0), "r"(b1));
}

__device__ __forceinline__ unsigned bf2_as_u(__nv_bfloat162 h) {
    return *(unsigned*)&h;
}
__device__ __forceinline__ __nv_bfloat162 u_as_bf2(unsigned u) {
    return *(__nv_bfloat162*)&u;
}

// split float pair -> hi bf16x2, lo bf16x2
__device__ __forceinline__ void split_bf2(float x, float y, unsigned& hi, unsigned& lo) {
    __nv_bfloat162 h = __float22bfloat162_rn(make_float2(x, y));
    float2 hf = __bfloat1622float2(h);
    __nv_bfloat162 l = __float22bfloat162_rn(make_float2(x - hf.x, y - hf.y));
    hi = bf2_as_u(h);
    lo = bf2_as_u(l);
}

// write one fp32 value as pre-split bf16 hi/lo into fragment-ordered array.
__device__ __forceinline__ void write_b_split(__nv_bfloat16* base, int n, int k,
                                              int kgs, float v) {
    int kg = k >> 4, r = k & 15;
    int word, t4;
    if (r < 8) { t4 = r >> 1; word = 0; }
    else       { t4 = (r - 8) >> 1; word = 1; }
    int half = r & 1;
    size_t bidx = ((((size_t)(n * kgs + kg) * 4 + t4) * 4 + word) * 2 + half);
    __nv_bfloat16 hi = __float2bfloat16(v);
    __nv_bfloat16 lo = __float2bfloat16(v - __bfloat162float(hi));
    base[bidx] = hi;
    base[bidx + 4] = lo;
}

// ---------------- kernel 1: pool partials + C + W2 + c0 + bias2 ----------
__global__ void k1_precompute(const float* __restrict__ gf,
                              const float* __restrict__ wq_l,
                              const float* __restrict__ wk_l,
                              const float* __restrict__ wv_l,
                              const float* __restrict__ wo_l,
                              const float* __restrict__ bq_l,
                              const float* __restrict__ bv_l,
                              const float* __restrict__ bo_l) {
    extern __shared__ float st[];
    int b = blockIdx.x, t = threadIdx.x;
    if (b < POOL_BLKS) {
        int r0 = b * ROWS_PER_BLK;
        int nrows = NN - r0;
        if (nrows > ROWS_PER_BLK) nrows = ROWS_PER_BLK;
        int tq = t & 127;          // float4 column group
        int tr = t >> 7;           // row offset 0..3
        const float4* p4 = (const float4*)gf;
        float4 a0 = make_float4(0.f, 0.f, 0.f, 0.f);
        float4 a1 = a0, a2 = a0, a3 = a0;
        for (int r = 0; r < nrows; r += 16) {
            int rr0 = r + tr;
            int rr1 = r + 4 + tr;
            int rr2 = r + 8 + tr;
            int rr3 = r + 12 + tr;
            if (rr0 < nrows) {
                float4 v = p4[(size_t)(r0 + rr0) * 128 + tq];
                a0.x += v.x; a0.y += v.y; a0.z += v.z; a0.w += v.w;
            }
            if (rr1 < nrows) {
                float4 v = p4[(size_t)(r0 + rr1) * 128 + tq];
                a1.x += v.x; a1.y += v.y; a1.z += v.z; a1.w += v.w;
            }
            if (rr2 < nrows) {
                float4 v = p4[(size_t)(r0 + rr2) * 128 + tq];
                a2.x += v.x; a2.y += v.y; a2.z += v.z; a2.w += v.w;
            }
            if (rr3 < nrows) {
                float4 v = p4[(size_t)(r0 + rr3) * 128 + tq];
                a3.x += v.x; a3.y += v.y; a3.z += v.z; a3.w += v.w;
            }
        }
        float4 acc = make_float4((a0.x + a1.x) + (a2.x + a3.x),
                                 (a0.y + a1.y) + (a2.y + a3.y),
                                 (a0.z + a1.z) + (a2.z + a3.z),
                                 (a0.w + a1.w) + (a2.w + a3.w));
        float4* st4 = (float4*)st;
        st4[tr * 128 + tq] = acc;
        __syncthreads();
        if (t < 128) {
            float4 s0 = st4[t], s1 = st4[128 + t], s2 = st4[256 + t], s3 = st4[384 + t];
            float4 s = make_float4((s0.x + s1.x) + (s2.x + s3.x),
                                   (s0.y + s1.y) + (s2.y + s3.y),
                                   (s0.z + s1.z) + (s2.z + s3.z),
                                   (s0.w + s1.w) + (s2.w + s3.w));
            ((float4*)g_partial)[b * 128 + t] = s;
        }
    } else if (b < POOL_BLKS + 128) {
        int i = b - POOL_BLKS;      // C k-row 0..127
        if (t < 256) {
            float a = 0.f;
            for (int h = 0; h < 128; ++h)
                a += __ldg(&wq_l[h * 128 + i]) * wk_l[h * 256 + t];
            write_b_split((__nv_bfloat16*)g_Cb4, t, i, 8, a);
        }
    } else if (b < POOL_BLKS + 384) {
        int j = b - (POOL_BLKS + 128);   // W2 k-index 0..255
        for (int idx = t; idx < 16384; idx += 512) {
            int h = idx >> 7, m = idx & 127;
            st[m * 132 + h] = wo_l[idx];
        }
        __syncthreads();
        if (t < 128) {
            float a = 0.f;
            for (int m = 0; m < 128; ++m)
                a += __ldg(&wv_l[m * 256 + j]) * st[m * 132 + t];
            write_b_split((__nv_bfloat16*)g_W2b4, t, j, 16, a);
        }
    } else if (b == POOL_BLKS + 384) {
        if (t < 256) {
            float a = 0.f;
            for (int h = 0; h < 128; ++h) a += bq_l[h] * wk_l[h * 256 + t];
            g_c0[t] = a;
        }
    } else {
        for (int idx = t; idx < 16384; idx += 512) {
            int h = idx >> 7, m = idx & 127;
            st[m * 132 + h] = wo_l[idx];
        }
        __syncthreads();
        if (t < 128) {
            float a = 0.f;
            for (int m = 0; m < 128; ++m) a += bv_l[m] * st[m * 132 + t];
            g_bias2[t] = a + bo_l[t];
        }
    }
}

// ---------------- kernel 1b: second-stage pool reduction (37 blocks) -----
__global__ void k1b_reduce() {
    int bb = blockIdx.x, t = threadIdx.x;
    float s0, s1, s2, s3;
    int base = bb * 8;
    s0 = g_partial[(base + 0) * 512 + t] + g_partial[(base + 4) * 512 + t];
    s1 = g_partial[(base + 1) * 512 + t] + g_partial[(base + 5) * 512 + t];
    s2 = g_partial[(base + 2) * 512 + t] + g_partial[(base + 6) * 512 + t];
    s3 = g_partial[(base + 3) * 512 + t] + g_partial[(base + 7) * 512 + t];
    g_partial2[bb * 512 + t] = (s0 + s1) + (s2 + s3);
}

// ---------------- kernel 2: pooled + global-path small matrices ----------
__global__ void k2_small(const float* __restrict__ wk_g,
                         const float* __restrict__ wv_g,
                         const float* __restrict__ wo_g,
                         const float* __restrict__ wq_g,
                         const float* __restrict__ bk_g,
                         const float* __restrict__ bv_g,
                         const float* __restrict__ bq_g,
                         float* __restrict__ out_pooled) {
    extern __shared__ float st[];       // 2 x 16896 floats
    float* st2 = st + 16896;
    int t = threadIdx.x;

    // reduce 37 second-stage partials (8-way ILP + 5 tail)
    {
        float s0 = 0.f, s1 = 0.f, s2 = 0.f, s3 = 0.f;
        float s4 = 0.f, s5 = 0.f, s6 = 0.f, s7 = 0.f;
        #pragma unroll
        for (int b = 0; b < 32; b += 8) {
            s0 += g_partial2[(b + 0) * 512 + t];
            s1 += g_partial2[(b + 1) * 512 + t];
            s2 += g_partial2[(b + 2) * 512 + t];
            s3 += g_partial2[(b + 3) * 512 + t];
            s4 += g_partial2[(b + 4) * 512 + t];
            s5 += g_partial2[(b + 5) * 512 + t];
            s6 += g_partial2[(b + 6) * 512 + t];
            s7 += g_partial2[(b + 7) * 512 + t];
        }
        s0 += g_partial2[32 * 512 + t];
        s1 += g_partial2[33 * 512 + t];
        s2 += g_partial2[34 * 512 + t];
        s3 += g_partial2[35 * 512 + t];
        s4 += g_partial2[36 * 512 + t];
        float s = ((s0 + s1) + (s2 + s3)) + ((s4 + s5) + (s6 + s7));
        s *= (1.0f / NN);
        g_pooled[t] = s;
        out_pooled[t] = s;
    }

    // stage wk_g and wv_g together (transposed)
    for (int idx = t; idx < 16384; idx += 512) {
        int h = idx >> 7, j = idx & 127;
        st[j * 132 + h]  = wk_g[idx];
        st2[j * 132 + h] = wv_g[idx];
    }
    __syncthreads();
    {
        int si = t >> 7, h = t & 127;
        float a = 0.f, a2 = 0.f;
        for (int j = 0; j < 128; ++j) {
            float p = g_pooled[si * 128 + j];
            a  += p * st[j * 132 + h];
            a2 += p * st2[j * 132 + h];
        }
        g_kg[t] = a + bk_g[h];
        g_vg[t] = a2 + bv_g[h];
    }
    __syncthreads();

    // stage wo_g and wq_g together (transposed)
    for (int idx = t; idx < 16384; idx += 512) {
        int h = idx >> 7, m = idx & 127;
        st[m * 132 + h]  = wo_g[idx];
        st2[m * 132 + h] = wq_g[idx];
    }
    __syncthreads();
    {
        int si = t >> 7, h = t & 127;
        float a = 0.f;
        for (int m = 0; m < 128; ++m) a += g_vg[si * 128 + m] * st[m * 132 + h];
        g_M[t] = a;
    }
    {
        int i = t >> 2, si = t & 3;
        float a = 0.f;
        for (int h = 0; h < 128; ++h) a += st2[i * 132 + h] * g_kg[si * 128 + h];
        g_kqg[i * 4 + si] = a;
    }
    if (t < 4) {
        float a = 0.f;
        for (int h = 0; h < 128; ++h) a += bq_g[h] * g_kg[t * 128 + h];
        g_cgs[t] = a;
    }
}

// ---------------- kernel 3: fused per-edge kernel (256 thr, 2 CTA/SM) ----
// Phase B stores pooled tile PRE-SPLIT (bf16 hi/lo words) into the sQK row
// footprint; Phase C A-fragments become direct LDS.32 (no cvt, half bytes).
__global__ void __launch_bounds__(256, 2)
main_edge_kernel(const float* __restrict__ ea_g,
                 const float* __restrict__ gf,
                 const int* __restrict__ ei,
                 const float* __restrict__ bo_g,
                 float* __restrict__ out,
                 float* __restrict__ attn_out) {
    extern __shared__ float smem[];
    unsigned* sEAhi = (unsigned*)smem;            // 64*68 uints
    unsigned* sEAlo = sEAhi + 64 * EA_U;          // 64*68 uints
    float*    sQK   = smem + 2 * 64 * EA_U;       // 64*260 floats
    const int tid  = threadIdx.x;
    const int wid  = tid >> 5;    // 0..7
    const int lane = tid & 31;
    const int g    = lane >> 2;   // 0..7
    const int t4   = lane & 3;    // 0..3
    const int e0   = blockIdx.x * TILE_E;

    // stage edge_attr tile pre-split to bf16 hi/lo (zero-fill OOB rows)
    for (int idx = tid; idx < 2048; idx += 256) {
        int r = idx >> 5, c = idx & 31;          // c: float4 col (k = 4c)
        float4 v = make_float4(0.f, 0.f, 0.f, 0.f);
        if (e0 + r < E_TOT) v = ((const float4*)ea_g)[(size_t)(e0 + r) * 32 + c];
        unsigned h0, l0, h1, l1;
        split_bf2(v.x, v.y, h0, l0);
        split_bf2(v.z, v.w, h1, l1);
        sEAhi[r * EA_U + 2 * c]     = h0;
        sEAhi[r * EA_U + 2 * c + 1] = h1;
        sEAlo[r * EA_U + 2 * c]     = l0;
        sEAlo[r * EA_U + 2 * c + 1] = l1;
    }
    __syncthreads();

    // ---- Phase A: qk[64][256] = ea @ C + c0 (bf16 m16n8k16, 3-term) ----
    {
        const int wm = wid >> 2;          // 0..1
        const int wn = wid & 3;           // 0..3
        const int m0 = wm * 32;
        const int n0 = wn * 64;
        float acc[2][8][4];
        #pragma unroll
        for (int am = 0; am < 2; ++am)
            #pragma unroll
            for (int bn = 0; bn < 8; ++bn)
                #pragma unroll
                for (int q = 0; q < 4; ++q) acc[am][bn][q] = 0.f;

        uint4 bpc[4], bpn[4];
        #pragma unroll
        for (int b2 = 0; b2 < 4; ++b2)
            bpc[b2] = __ldg(&g_Cb4[((n0 + 8 * b2 + g) * 8 + 0) * 4 + t4]);

        #pragma unroll 1
        for (int kg = 0; kg < 8; ++kg) {
            unsigned Ah[2][4], Al[2][4];
            #pragma unroll
            for (int am = 0; am < 2; ++am) {
                int R = m0 + 16 * am;
                Ah[am][0] = sEAhi[(R + g)     * EA_U + kg * 8 + t4];
                Ah[am][1] = sEAhi[(R + g + 8) * EA_U + kg * 8 + t4];
                Ah[am][2] = sEAhi[(R + g)     * EA_U + kg * 8 + 4 + t4];
                Ah[am][3] = sEAhi[(R + g + 8) * EA_U + kg * 8 + 4 + t4];
                Al[am][0] = sEAlo[(R + g)     * EA_U + kg * 8 + t4];
                Al[am][1] = sEAlo[(R + g + 8) * EA_U + kg * 8 + t4];
                Al[am][2] = sEAlo[(R + g)     * EA_U + kg * 8 + 4 + t4];
                Al[am][3] = sEAlo[(R + g + 8) * EA_U + kg * 8 + 4 + t4];
            }
            #pragma unroll
            for (int b2 = 0; b2 < 4; ++b2)
                bpn[b2] = __ldg(&g_Cb4[((n0 + 32 + 8 * b2 + g) * 8 + kg) * 4 + t4]);
            #pragma unroll
            for (int b2 = 0; b2 < 4; ++b2) {
                #pragma unroll
                for (int am = 0; am < 2; ++am) {
                    mma16(acc[am][b2], Ah[am], bpc[b2].x, bpc[b2].y);
                    mma16(acc[am][b2], Ah[am], bpc[b2].z, bpc[b2].w);
                    mma16(acc[am][b2], Al[am], bpc[b2].x, bpc[b2].y);
                }
            }
            if (kg < 7) {
                #pragma unroll
                for (int b2 = 0; b2 < 4; ++b2)
                    bpc[b2] = __ldg(&g_Cb4[((n0 + 8 * b2 + g) * 8 + kg + 1) * 4 + t4]);
            }
            #pragma unroll
            for (int b2 = 0; b2 < 4; ++b2) {
                #pragma unroll
                for (int am = 0; am < 2; ++am) {
                    mma16(acc[am][4 + b2], Ah[am], bpn[b2].x, bpn[b2].y);
                    mma16(acc[am][4 + b2], Ah[am], bpn[b2].z, bpn[b2].w);
                    mma16(acc[am][4 + b2], Al[am], bpn[b2].x, bpn[b2].y);
                }
            }
        }

        // epilogue: qk + c0 -> sQK (fp32, consumed by Phase B scores)
        #pragma unroll
        for (int am = 0; am < 2; ++am) {
            #pragma unroll
            for (int bn = 0; bn < 8; ++bn) {
                int col = n0 + 8 * bn + 2 * t4;
                float2 c0v = *(const float2*)&g_c0[col];
                int r1 = m0 + 16 * am + g;
                *(float2*)&sQK[r1 * QK_S + col] =
                    make_float2(acc[am][bn][0] + c0v.x, acc[am][bn][1] + c0v.y);
                *(float2*)&sQK[(r1 + 8) * QK_S + col] =
                    make_float2(acc[am][bn][2] + c0v.x, acc[am][bn][3] + c0v.y);
            }
        }
    }
    __syncthreads();

    // ---- Phase B: gather + local softmax + pooled feats + global path ----
    int idx0[8], idx1[8];
    #pragma unroll
    for (int r = 0; r < 8; ++r) {
        int eg = e0 + 8 * wid + r;
        int egc = eg < E_TOT ? eg : E_TOT - 1;
        idx0[r] = ei[egc];
        idx1[r] = ei[E_TOT + egc];
    }
    #pragma unroll 2
    for (int r = 0; r < 8; ++r) {
        int el = 8 * wid + r;
        int eg = e0 + el;
        if (eg < E_TOT) {
            const float4* srcp = (const float4*)(gf + (size_t)idx0[r] * 512);
            const float4* dstp = (const float4*)(gf + (size_t)idx1[r] * 512);
            float4 sv[4], dv[4];
            #pragma unroll
            for (int s2 = 0; s2 < 4; ++s2) {
                sv[s2] = srcp[s2 * 32 + lane];
                dv[s2] = dstp[s2 * 32 + lane];
            }

            // gather-independent work under the loads
            unsigned hu0 = sEAhi[el * EA_U + 2 * lane];
            unsigned hu1 = sEAhi[el * EA_U + 2 * lane + 1];
            unsigned lu0 = sEAlo[el * EA_U + 2 * lane];
            unsigned lu1 = sEAlo[el * EA_U + 2 * lane + 1];
            float2 hf0 = __bfloat1622float2(u_as_bf2(hu0));
            float2 hf1 = __bfloat1622float2(u_as_bf2(hu1));
            float2 lf0 = __bfloat1622float2(u_as_bf2(lu0));
            float2 lf1 = __bfloat1622float2(u_as_bf2(lu1));
            float4 eav = make_float4(hf0.x + lf0.x, hf0.y + lf0.y,
                                     hf1.x + lf1.x, hf1.y + lf1.y);
            float4 kq0 = ((const float4*)g_kqg)[4 * lane + 0];
            float4 kq1 = ((const float4*)g_kqg)[4 * lane + 1];
            float4 kq2 = ((const float4*)g_kqg)[4 * lane + 2];
            float4 kq3 = ((const float4*)g_kqg)[4 * lane + 3];
            float g0 = eav.x*kq0.x + eav.y*kq1.x + eav.z*kq2.x + eav.w*kq3.x;
            float g1 = eav.x*kq0.y + eav.y*kq1.y + eav.z*kq2.y + eav.w*kq3.y;
            float g2 = eav.x*kq0.z + eav.y*kq1.z + eav.z*kq2.z + eav.w*kq3.z;
            float g3 = eav.x*kq0.w + eav.y*kq1.w + eav.z*kq2.w + eav.w*kq3.w;
            float4 qlo = *(const float4*)&sQK[el * QK_S + 4 * lane];
            float4 qhi = *(const float4*)&sQK[el * QK_S + 128 + 4 * lane];

            float sc0 = dot4(qlo, sv[0]) + dot4(qhi, dv[0]);
            float sc1 = dot4(qlo, sv[1]) + dot4(qhi, dv[1]);
            float sc2 = dot4(qlo, sv[2]) + dot4(qhi, dv[2]);
            float sc3 = dot4(qlo, sv[3]) + dot4(qhi, dv[3]);

            // merged 8-value butterfly reduction
            #pragma unroll
            for (int o = 16; o > 0; o >>= 1) {
                sc0 += __shfl_xor_sync(0xFFFFFFFFu, sc0, o);
                sc1 += __shfl_xor_sync(0xFFFFFFFFu, sc1, o);
                sc2 += __shfl_xor_sync(0xFFFFFFFFu, sc2, o);
                sc3 += __shfl_xor_sync(0xFFFFFFFFu, sc3, o);
                g0  += __shfl_xor_sync(0xFFFFFFFFu, g0, o);
                g1  += __shfl_xor_sync(0xFFFFFFFFu, g1, o);
                g2  += __shfl_xor_sync(0xFFFFFFFFu, g2, o);
                g3  += __shfl_xor_sync(0xFFFFFFFFu, g3, o);
            }

            float z0 = sc0 * SCALE, z1 = sc1 * SCALE, z2 = sc2 * SCALE, z3 = sc3 * SCALE;
            float mz = fmaxf(fmaxf(z0, z1), fmaxf(z2, z3));
            float a0 = __expf(z0 - mz), a1 = __expf(z1 - mz);
            float a2 = __expf(z2 - mz), a3 = __expf(z3 - mz);
            float inv = 1.f / (a0 + a1 + a2 + a3);
            a0 *= inv; a1 *= inv; a2 *= inv; a3 *= inv;
            float4 plo, phi;
            plo.x = a0*sv[0].x + a1*sv[1].x + a2*sv[2].x + a3*sv[3].x;
            plo.y = a0*sv[0].y + a1*sv[1].y + a2*sv[2].y + a3*sv[3].y;
            plo.z = a0*sv[0].z + a1*sv[1].z + a2*sv[2].z + a3*sv[3].z;
            plo.w = a0*sv[0].w + a1*sv[1].w + a2*sv[2].w + a3*sv[3].w;
            phi.x = a0*dv[0].x + a1*dv[1].x + a2*dv[2].x + a3*dv[3].x;
            phi.y = a0*dv[0].y + a1*dv[1].y + a2*dv[2].y + a3*dv[3].y;
            phi.z = a0*dv[0].z + a1*dv[1].z + a2*dv[2].z + a3*dv[3].z;
            phi.w = a0*dv[0].w + a1*dv[1].w + a2*dv[2].w + a3*dv[3].w;

            // pre-split pooled values; store into sQK row as bf16 hi/lo words:
            // words [0..63]=hi(plo part), [64..127]=hi(phi part),
            // words [128..191]=lo(plo), [192..255]=lo(phi).
            {
                unsigned ph0, pl0, ph1, pl1, qh0, ql0, qh1, ql1;
                split_bf2(plo.x, plo.y, ph0, pl0);
                split_bf2(plo.z, plo.w, ph1, pl1);
                split_bf2(phi.x, phi.y, qh0, ql0);
                split_bf2(phi.z, phi.w, qh1, ql1);
                unsigned* rowp = (unsigned*)&sQK[el * QK_S];
                *(uint2*)&rowp[2 * lane]        = make_uint2(ph0, ph1);
                *(uint2*)&rowp[64 + 2 * lane]   = make_uint2(qh0, qh1);
                *(uint2*)&rowp[128 + 2 * lane]  = make_uint2(pl0, pl1);
                *(uint2*)&rowp[192 + 2 * lane]  = make_uint2(ql0, ql1);
            }

            float y0 = (g0 + g_cgs[0]) * SCALE, y1 = (g1 + g_cgs[1]) * SCALE;
            float y2 = (g2 + g_cgs[2]) * SCALE, y3 = (g3 + g_cgs[3]) * SCALE;
            float my = fmaxf(fmaxf(y0, y1), fmaxf(y2, y3));
            float b0 = __expf(y0 - my), b1 = __expf(y1 - my);
            float b2 = __expf(y2 - my), b3 = __expf(y3 - my);
            float binv = 1.f / (b0 + b1 + b2 + b3);
            b0 *= binv; b1 *= binv; b2 *= binv; b3 *= binv;
            if (lane == 0) {
                float* ap = attn_out + (size_t)eg * 4;
                ap[0] = b0; ap[1] = b1; ap[2] = b2; ap[3] = b3;
            }
            float4 m0v = ((const float4*)g_M)[lane];
            float4 m1v = ((const float4*)g_M)[32 + lane];
            float4 m2v = ((const float4*)g_M)[64 + lane];
            float4 m3v = ((const float4*)g_M)[96 + lane];
            float4 bo4 = ((const float4*)bo_g)[lane];
            float4 go;
            go.x = b0*m0v.x + b1*m1v.x + b2*m2v.x + b3*m3v.x + bo4.x;
            go.y = b0*m0v.y + b1*m1v.y + b2*m2v.y + b3*m3v.y + bo4.y;
            go.z = b0*m0v.z + b1*m1v.z + b2*m2v.z + b3*m3v.z + bo4.z;
            go.w = b0*m0v.w + b1*m1v.w + b2*m2v.w + b3*m3v.w + bo4.w;
            float* orow = out + (size_t)eg * 384;
            ((float4*)orow)[lane] = eav;
            ((float4*)(orow + 256))[lane] = go;
        }
    }
    __syncthreads();

    // ---- Phase C: local_out[64][128] = pooled @ W2^T + bias2 (bf16) ----
    // A-fragments are pre-split bf16 words in sQK rows: word kg*8+t4 = k pair
    // (2t4,2t4+1), +4 words = k pair (+8,+9); lo at word offset +128.
    {
        const int cm = wid >> 2;         // 0..1
        const int cn = wid & 3;          // 0..3
        const int m0 = cm * 32;
        const int n0 = cn * 32;
        float acc[2][4][4];
        #pragma unroll
        for (int am = 0; am < 2; ++am)
            #pragma unroll
            for (int bn = 0; bn < 4; ++bn)
                #pragma unroll
                for (int q = 0; q < 4; ++q) acc[am][bn][q] = 0.f;

        uint4 bp0[4], bp1[4];
        #pragma unroll
        for (int bn = 0; bn < 4; ++bn)
            bp0[bn] = __ldg(&g_W2b4[((n0 + 8 * bn + g) * 16 + 0) * 4 + t4]);

        #pragma unroll 1
        for (int kg = 0; kg < 16; kg += 2) {
            #pragma unroll
            for (int bn = 0; bn < 4; ++bn)
                bp1[bn] = __ldg(&g_W2b4[((n0 + 8 * bn + g) * 16 + kg + 1) * 4 + t4]);

            {
                unsigned Ah[2][4], Al[2][4];
                #pragma unroll
                for (int am = 0; am < 2; ++am) {
                    int R = m0 + 16 * am;
                    const unsigned* r0p = (const unsigned*)&sQK[(R + g)     * QK_S];
                    const unsigned* r1p = (const unsigned*)&sQK[(R + g + 8) * QK_S];
                    Ah[am][0] = r0p[kg * 8 + t4];
                    Ah[am][1] = r1p[kg * 8 + t4];
                    Ah[am][2] = r0p[kg * 8 + 4 + t4];
                    Ah[am][3] = r1p[kg * 8 + 4 + t4];
                    Al[am][0] = r0p[128 + kg * 8 + t4];
                    Al[am][1] = r1p[128 + kg * 8 + t4];
                    Al[am][2] = r0p[128 + kg * 8 + 4 + t4];
                    Al[am][3] = r1p[128 + kg * 8 + 4 + t4];
                }
                #pragma unroll
                for (int bn = 0; bn < 4; ++bn) {
                    #pragma unroll
                    for (int am = 0; am < 2; ++am) {
                        mma16(acc[am][bn], Ah[am], bp0[bn].x, bp0[bn].y);
                        mma16(acc[am][bn], Ah[am], bp0[bn].z, bp0[bn].w);
                        mma16(acc[am][bn], Al[am], bp0[bn].x, bp0[bn].y);
                    }
                }
            }

            if (kg + 2 < 16) {
                #pragma unroll
                for (int bn = 0; bn < 4; ++bn)
                    bp0[bn] = __ldg(&g_W2b4[((n0 + 8 * bn + g) * 16 + kg + 2) * 4 + t4]);
            }

            {
                unsigned Ah[2][4], Al[2][4];
                #pragma unroll
                for (int am = 0; am < 2; ++am) {
                    int R = m0 + 16 * am;
                    const unsigned* r0p = (const unsigned*)&sQK[(R + g)     * QK_S];
                    const unsigned* r1p = (const unsigned*)&sQK[(R + g + 8) * QK_S];
                    Ah[am][0] = r0p[(kg + 1) * 8 + t4];
                    Ah[am][1] = r1p[(kg + 1) * 8 + t4];
                    Ah[am][2] = r0p[(kg + 1) * 8 + 4 + t4];
                    Ah[am][3] = r1p[(kg + 1) * 8 + 4 + t4];
                    Al[am][0] = r0p[128 + (kg + 1) * 8 + t4];
                    Al[am][1] = r1p[128 + (kg + 1) * 8 + t4];
                    Al[am][2] = r0p[128 + (kg + 1) * 8 + 4 + t4];
                    Al[am][3] = r1p[128 + (kg + 1) * 8 + 4 + t4];
                }
                #pragma unroll
                for (int bn = 0; bn < 4; ++bn) {
                    #pragma unroll
                    for (int am = 0; am < 2; ++am) {
                        mma16(acc[am][bn], Ah[am], bp1[bn].x, bp1[bn].y);
                        mma16(acc[am][bn], Ah[am], bp1[bn].z, bp1[bn].w);
                        mma16(acc[am][bn], Al[am], bp1[bn].x, bp1[bn].y);
                    }
                }
            }
        }

        // epilogue: + bias2 -> out[:, 128:256]
        #pragma unroll
        for (int am = 0; am < 2; ++am) {
            #pragma unroll
            for (int bn = 0; bn < 4; ++bn) {
                int h = n0 + 8 * bn + 2 * t4;
                float2 bv = *(const float2*)&g_bias2[h];
                int e1 = e0 + m0 + 16 * am + g;
                if (e1 < E_TOT) {
                    *(float2*)&out[(size_t)e1 * 384 + 128 + h] =
                        make_float2(acc[am][bn][0] + bv.x, acc[am][bn][1] + bv.y);
                }
                int e2 = e1 + 8;
                if (e2 < E_TOT) {
                    *(float2*)&out[(size_t)e2 * 384 + 128 + h] =
                        make_float2(acc[am][bn][2] + bv.x, acc[am][bn][3] + bv.y);
                }
            }
        }
    }
}

// ---------------- launch ---------------------------------------------------
extern "C" void kernel_launch(void* const* d_in, const int* in_sizes, int n_in,
                              void* d_out, int out_size) {
    const float* ea   = (const float*)d_in[0];
    const float* gf   = (const float*)d_in[1];
    const int*   ei   = (const int*)d_in[2];
    const float* wq_l = (const float*)d_in[3];
    const float* wk_l = (const float*)d_in[4];
    const float* wv_l = (const float*)d_in[5];
    const float* bq_l = (const float*)d_in[6];
    const float* bv_l = (const float*)d_in[8];
    const float* wo_l = (const float*)d_in[9];
    const float* bo_l = (const float*)d_in[10];
    const float* wq_g = (const float*)d_in[11];
    const float* wk_g = (const float*)d_in[12];
    const float* wv_g = (const float*)d_in[13];
    const float* bq_g = (const float*)d_in[14];
    const float* bk_g = (const float*)d_in[15];
    const float* bv_g = (const float*)d_in[16];
    const float* wo_g = (const float*)d_in[17];
    const float* bo_g = (const float*)d_in[18];

    float* out        = (float*)d_out;
    float* out_pooled = out + (size_t)E_TOT * 384;
    float* out_attn   = out_pooled + 512;

    const int MAIN_SMEM = (2 * 64 * EA_U + 16640) * 4;   // 101376 B
    const int K2_SMEM   = 2 * 16896 * 4;                  // 135168 B

    cudaFuncSetAttribute(k1_precompute,
                         cudaFuncAttributeMaxDynamicSharedMemorySize, 67584);
    cudaFuncSetAttribute(k2_small,
                         cudaFuncAttributeMaxDynamicSharedMemorySize, K2_SMEM);
    cudaFuncSetAttribute(main_edge_kernel,
                         cudaFuncAttributeMaxDynamicSharedMemorySize, MAIN_SMEM);

    k1_precompute<<<POOL_BLKS + 386, 512, 67584>>>(gf, wq_l, wk_l, wv_l, wo_l,
                                                   bq_l, bv_l, bo_l);
    k1b_reduce<<<POOL2_BLKS, 512>>>();
    k2_small<<<1, 512, K2_SMEM>>>(wk_g, wv_g, wo_g, wq_g,
                                  bk_g, bv_g, bq_g, out_pooled);
    main_edge_kernel<<<GRID_MAIN, 256, MAIN_SMEM>>>(ea, gf, ei, bo_g, out, out_attn);
}